// round 1
// baseline (speedup 1.0000x reference)
#include <cuda_runtime.h>
#include <math.h>
#include <stdint.h>

// ---------------- problem constants ----------------
#define BB   32
#define HH   28
#define WW   28
#define C1   64
#define DD   256
#define NHH  8
#define HDIM 32
#define SS   784            // HH*WW
#define TOT  (BB*C1*SS)     // 1,605,632
#define KSEL 803            // ceil(0.0005 * TOT)

#define SW_OFF   8192                      // pooled = 32*256
#define SW_SIZE  (BB*SS*C1)                // 1,605,632
#define IDX_OFF  (SW_OFF + SW_SIZE)        // 1,613,824
#define OUT_FULL (IDX_OFF + BB*SS*2)       // 1,664,000

// ---------------- device scratch ----------------
__device__ __align__(16) float g_A[TOT];                 // conv output (B,C1,S)
__device__ __align__(16) float g_pe[SS*DD];              // positional encoding
__device__ __align__(16) float g_qkv0[SS*3*DD];          // PE @ Wqkv^T + b
__device__ __align__(16) float g_qkv[BB*SS*3*DD];        // per (b,s) qkv
__device__ __align__(16) float g_ctx[BB*SS*DD];          // attention context
__device__ __align__(16) float g_U[BB*SS*DD];            // sparse mix rows (compact)
__device__ int      g_actrow[BB*SS];
__device__ unsigned g_hist1[2048];
__device__ unsigned g_hist2[2048];
__device__ unsigned g_hist3[1024];
__device__ unsigned g_prefix;
__device__ int      g_krem;
__device__ float    g_thresh;
__device__ int      g_nact;

// ---------------- init: zero hists/counters ----------------
__global__ void k_zero() {
    int t = threadIdx.x;
    for (int i = t; i < 2048; i += 256) { g_hist1[i] = 0; g_hist2[i] = 0; }
    for (int i = t; i < 1024; i += 256) g_hist3[i] = 0;
    if (t == 0) { g_prefix = 0; g_krem = KSEL; g_nact = 0; g_thresh = 0.f; }
}

// ---------------- positional encoding ----------------
__global__ void k_pe() {
    int s = blockIdx.x;            // 0..783
    int d = threadIdx.x;           // 0..255
    int h = s / WW, w = s % WW;
    int i2 = d & ~1;               // even base index (= 2i)
    float div = expf((float)i2 * (-logf(10000.0f) / (float)DD));
    float val = (d & 1) ? cosf((float)w * div) : sinf((float)h * div);
    g_pe[s * DD + d] = val;
}

// ---------------- conv 9x9 + relu ----------------
__global__ void k_conv(const float* __restrict__ x, const float* __restrict__ cw) {
    __shared__ float xs[36][36];
    __shared__ float ws[8][81];
    int b = blockIdx.x, cg = blockIdx.y;   // cg: channel group of 8
    int t = threadIdx.x;
    for (int e = t; e < 36*36; e += 256) {
        int r = e / 36, c = e % 36;
        int hh = r - 4, ww = c - 4;
        xs[r][c] = (hh >= 0 && hh < HH && ww >= 0 && ww < WW) ? x[b*SS + hh*WW + ww] : 0.f;
    }
    for (int e = t; e < 8*81; e += 256) {
        int c8 = e / 81, k = e % 81;
        ws[c8][k] = cw[(cg*8 + c8)*81 + k];
    }
    __syncthreads();
    for (int c8 = 0; c8 < 8; c8++) {
        for (int p = t; p < SS; p += 256) {
            int hh = p / WW, ww = p % WW;
            float acc = 0.f;
#pragma unroll
            for (int ky = 0; ky < 9; ky++)
#pragma unroll
                for (int kx = 0; kx < 9; kx++)
                    acc += xs[hh+ky][ww+kx] * ws[c8][ky*9 + kx];
            g_A[((b*C1) + cg*8 + c8)*SS + p] = fmaxf(acc, 0.f);
        }
    }
}

// ---------------- radix-select histograms ----------------
__global__ void k_hist1() {
    __shared__ unsigned sh[2048];
    int t = threadIdx.x;
    for (int i = t; i < 2048; i += 256) sh[i] = 0;
    __syncthreads();
    for (int idx = blockIdx.x*256 + t; idx < TOT; idx += gridDim.x*256) {
        unsigned u = __float_as_uint(g_A[idx]);
        if (u) atomicAdd(&sh[u >> 21], 1u);
    }
    __syncthreads();
    for (int i = t; i < 2048; i += 256) { unsigned v = sh[i]; if (v) atomicAdd(&g_hist1[i], v); }
}
__global__ void k_hist2() {
    __shared__ unsigned sh[2048];
    int t = threadIdx.x;
    for (int i = t; i < 2048; i += 256) sh[i] = 0;
    __syncthreads();
    unsigned pf = g_prefix;
    for (int idx = blockIdx.x*256 + t; idx < TOT; idx += gridDim.x*256) {
        unsigned u = __float_as_uint(g_A[idx]);
        if (u && (u >> 21) == pf) atomicAdd(&sh[(u >> 10) & 0x7FF], 1u);
    }
    __syncthreads();
    for (int i = t; i < 2048; i += 256) { unsigned v = sh[i]; if (v) atomicAdd(&g_hist2[i], v); }
}
__global__ void k_hist3() {
    __shared__ unsigned sh[1024];
    int t = threadIdx.x;
    for (int i = t; i < 1024; i += 256) sh[i] = 0;
    __syncthreads();
    unsigned pf = g_prefix;
    for (int idx = blockIdx.x*256 + t; idx < TOT; idx += gridDim.x*256) {
        unsigned u = __float_as_uint(g_A[idx]);
        if (u && (u >> 10) == pf) atomicAdd(&sh[u & 0x3FF], 1u);
    }
    __syncthreads();
    for (int i = t; i < 1024; i += 256) { unsigned v = sh[i]; if (v) atomicAdd(&g_hist3[i], v); }
}

// scan: find bin where suffix-cumulative crosses k; level 1/2 refine prefix, level 3 -> threshold
__global__ void k_scan(int level) {
    const unsigned* hist = (level == 1) ? g_hist1 : (level == 2) ? g_hist2 : g_hist3;
    int nbins = (level == 3) ? 1024 : 2048;
    int final_ = (level == 3);
    __shared__ unsigned part[256];
    __shared__ unsigned suf[256];
    int t = threadIdx.x;
    int chunk = nbins / 256;       // 8 or 4
    unsigned loc[8];
    unsigned psum = 0;
    for (int i = 0; i < chunk; i++) { loc[i] = hist[t*chunk + i]; psum += loc[i]; }
    part[t] = psum; suf[t] = psum;
    __syncthreads();
    for (int off = 1; off < 256; off <<= 1) {
        unsigned v = suf[t];
        if (t + off < 256) v += suf[t + off];
        __syncthreads();
        suf[t] = v;
        __syncthreads();
    }
    unsigned k = (unsigned)g_krem;
    unsigned total = suf[0];
    if (total < k) {
        if (t == 0) { if (final_) g_thresh = 0.f; else g_prefix = 0xFFFFFFFFu; }
        return;
    }
    unsigned above = suf[t] - part[t];
    if (above < k && suf[t] >= k) {
        unsigned cum = above;
        for (int i = chunk - 1; i >= 0; i--) {
            cum += loc[i];
            if (cum >= k) {
                unsigned sel = (unsigned)(t*chunk + i);
                if (final_) g_thresh = __uint_as_float((g_prefix << 10) | sel);
                else { g_prefix = (g_prefix << 11) | sel; g_krem = (int)(k - (cum - loc[i])); }
                break;
            }
        }
    }
}

// ---------------- per-pixel sparse softmax + outputs + compact U ----------------
__global__ void k_sparse(const float* __restrict__ emb, float* __restrict__ out, int full_out) {
    int p = blockIdx.x*256 + threadIdx.x;
    if (p >= BB*SS) return;
    int b = p / SS, s = p % SS;
    float thr = g_thresh;
    float m1 = -INFINITY, m2 = -INFINITY;
    int i1 = 0, i2 = 0, cnt = 0;
    const float* ap = g_A + (size_t)b*C1*SS + s;
#pragma unroll 8
    for (int c = 0; c < C1; c++) {
        float a = ap[c*SS];
        float v = (a >= thr) ? a : 0.f;
        if (v > 0.f) cnt++;
        if (v > m1) { m2 = m1; i2 = i1; m1 = v; i1 = c; }
        else if (v > m2) { m2 = v; i2 = c; }
    }
    float wA = 0.f, wB = 0.f;
    if (cnt == 1) wA = 1.f;
    else if (cnt >= 2) {
        float e2 = expf(m2 - m1);
        float z = 1.f + e2;
        wA = 1.f / z; wB = e2 / z;
    }
    if (full_out) {
        float* sw = out + SW_OFF + (size_t)p*C1;
        for (int c = 0; c < C1; c++) {
            float o = 0.f;
            if (c == i1) o = wA; else if (c == i2) o = wB;
            sw[c] = o;
        }
        out[IDX_OFF + p*2]     = (float)i1;
        out[IDX_OFF + p*2 + 1] = (float)i2;
    }
    if (cnt > 0) {
        int slot = atomicAdd(&g_nact, 1);
        g_actrow[slot] = p;
        float w2v = (cnt >= 2) ? wB : 0.f;
        float* up = g_U + (size_t)slot*DD;
        const float* e1p = emb + i1*DD;
        const float* e2p = emb + i2*DD;
        for (int d = 0; d < DD; d++) up[d] = wA*e1p[d] + w2v*e2p[d];
    }
}

// ---------------- qkv0 = PE @ Wqkv^T + b   (784 x 768, K=256) ----------------
__global__ void k_qkv0(const float* __restrict__ Wq, const float* __restrict__ bias) {
    __shared__ float As[16][68];
    __shared__ float Bs[16][68];
    int tx = threadIdx.x % 16, ty = threadIdx.x / 16;
    int m0 = blockIdx.x*64, n0 = blockIdx.y*64;
    float acc[4][4] = {};
    int lr = threadIdx.x / 4;
    int lk = (threadIdx.x % 4) * 4;
    for (int k0 = 0; k0 < DD; k0 += 16) {
        float4 av = (m0 + lr < SS) ? *(const float4*)&g_pe[(m0+lr)*DD + k0 + lk] : make_float4(0,0,0,0);
        float4 bv = *(const float4*)&Wq[(n0+lr)*DD + k0 + lk];
        __syncthreads();
        As[lk+0][lr] = av.x; As[lk+1][lr] = av.y; As[lk+2][lr] = av.z; As[lk+3][lr] = av.w;
        Bs[lk+0][lr] = bv.x; Bs[lk+1][lr] = bv.y; Bs[lk+2][lr] = bv.z; Bs[lk+3][lr] = bv.w;
        __syncthreads();
#pragma unroll
        for (int kk = 0; kk < 16; kk++) {
            float4 a4 = *(const float4*)&As[kk][ty*4];
            float4 b4 = *(const float4*)&Bs[kk][tx*4];
            float sa[4] = {a4.x, a4.y, a4.z, a4.w};
            float sb[4] = {b4.x, b4.y, b4.z, b4.w};
#pragma unroll
            for (int i = 0; i < 4; i++)
#pragma unroll
                for (int j = 0; j < 4; j++)
                    acc[i][j] += sa[i]*sb[j];
        }
    }
#pragma unroll
    for (int i = 0; i < 4; i++) {
        int m = m0 + ty*4 + i;
        if (m < SS)
#pragma unroll
            for (int j = 0; j < 4; j++) {
                int n = n0 + tx*4 + j;
                g_qkv0[m*768 + n] = acc[i][j] + bias[n];
            }
    }
}

// ---------------- broadcast qkv0 to all batches ----------------
__global__ void k_bcast() {
    int idx = blockIdx.x*256 + threadIdx.x;            // float4 index; grid covers exactly
    int n4 = idx % 192;
    int bsrow = idx / 192;
    int s = bsrow % SS;
    const float4* src = (const float4*)g_qkv0;
    float4* dst = (float4*)g_qkv;
    dst[idx] = src[s*192 + n4];
}

// ---------------- delta = U @ Wqkv^T, scatter-add into qkv ----------------
__global__ void k_delta(const float* __restrict__ Wq) {
    int nact = g_nact;
    int m0 = blockIdx.x*64;
    if (m0 >= nact) return;
    __shared__ float As[16][68];
    __shared__ float Bs[16][68];
    int tx = threadIdx.x % 16, ty = threadIdx.x / 16;
    int n0 = blockIdx.y*64;
    float acc[4][4] = {};
    int lr = threadIdx.x / 4;
    int lk = (threadIdx.x % 4) * 4;
    for (int k0 = 0; k0 < DD; k0 += 16) {
        float4 av = (m0 + lr < nact) ? *(const float4*)&g_U[(size_t)(m0+lr)*DD + k0 + lk] : make_float4(0,0,0,0);
        float4 bv = *(const float4*)&Wq[(n0+lr)*DD + k0 + lk];
        __syncthreads();
        As[lk+0][lr] = av.x; As[lk+1][lr] = av.y; As[lk+2][lr] = av.z; As[lk+3][lr] = av.w;
        Bs[lk+0][lr] = bv.x; Bs[lk+1][lr] = bv.y; Bs[lk+2][lr] = bv.z; Bs[lk+3][lr] = bv.w;
        __syncthreads();
#pragma unroll
        for (int kk = 0; kk < 16; kk++) {
            float4 a4 = *(const float4*)&As[kk][ty*4];
            float4 b4 = *(const float4*)&Bs[kk][tx*4];
            float sa[4] = {a4.x, a4.y, a4.z, a4.w};
            float sb[4] = {b4.x, b4.y, b4.z, b4.w};
#pragma unroll
            for (int i = 0; i < 4; i++)
#pragma unroll
                for (int j = 0; j < 4; j++)
                    acc[i][j] += sa[i]*sb[j];
        }
    }
#pragma unroll
    for (int i = 0; i < 4; i++) {
        int m = m0 + ty*4 + i;
        if (m < nact) {
            int p = g_actrow[m];
            float* dst = g_qkv + (size_t)p*768 + n0 + tx*4;
#pragma unroll
            for (int j = 0; j < 4; j++) dst[j] += acc[i][j];
        }
    }
}

// ---------------- flash attention per (q-tile, head, batch) ----------------
__global__ void k_flash() {
    __shared__ __align__(16) float Qs[32][68];
    __shared__ __align__(16) float Ks[32][68];
    __shared__ __align__(16) float Vs[64][34];
    __shared__ __align__(16) float Ps[64][68];
    int b = blockIdx.z, h = blockIdx.y;
    int q0 = blockIdx.x * 64;
    int t = threadIdx.x;
    int tx = t % 16, ty = t / 16;
    const float scale = 0.17677669529663689f;  // 1/sqrt(32)

    for (int e = t; e < 64*32; e += 256) {
        int r = e >> 5, d = e & 31;
        int gr = q0 + r;
        Qs[d][r] = (gr < SS) ? g_qkv[(size_t)(b*SS + gr)*768 + h*HDIM + d] * scale : 0.f;
    }
    float m_i[4], l_i[4], accO[4][2];
#pragma unroll
    for (int i = 0; i < 4; i++) { m_i[i] = -INFINITY; l_i[i] = 0.f; accO[i][0] = 0.f; accO[i][1] = 0.f; }
    __syncthreads();

    for (int k0 = 0; k0 < SS; k0 += 64) {
        for (int e = t; e < 64*32; e += 256) {
            int r = e >> 5, d = e & 31;
            int gr = k0 + r;
            float kv = 0.f, vv = 0.f;
            if (gr < SS) {
                size_t base = (size_t)(b*SS + gr)*768 + h*HDIM;
                kv = g_qkv[base + DD + d];
                vv = g_qkv[base + 2*DD + d];
            }
            Ks[d][r] = kv;
            Vs[r][d] = vv;
        }
        __syncthreads();

        float s[4][4] = {};
#pragma unroll
        for (int kk = 0; kk < 32; kk++) {
            float4 a4 = *(const float4*)&Qs[kk][ty*4];
            float4 b4 = *(const float4*)&Ks[kk][tx*4];
            float sa[4] = {a4.x, a4.y, a4.z, a4.w};
            float sb[4] = {b4.x, b4.y, b4.z, b4.w};
#pragma unroll
            for (int i = 0; i < 4; i++)
#pragma unroll
                for (int j = 0; j < 4; j++)
                    s[i][j] += sa[i]*sb[j];
        }

#pragma unroll
        for (int i = 0; i < 4; i++) {
#pragma unroll
            for (int j = 0; j < 4; j++)
                if (k0 + tx*4 + j >= SS) s[i][j] = -1e30f;
            float rm = fmaxf(fmaxf(s[i][0], s[i][1]), fmaxf(s[i][2], s[i][3]));
#pragma unroll
            for (int off = 8; off >= 1; off >>= 1)
                rm = fmaxf(rm, __shfl_xor_sync(0xffffffffu, rm, off));
            float mn = fmaxf(m_i[i], rm);
            float alpha = expf(m_i[i] - mn);
            float rs = 0.f;
#pragma unroll
            for (int j = 0; j < 4; j++) {
                float pv = expf(s[i][j] - mn);
                s[i][j] = pv;
                rs += pv;
            }
#pragma unroll
            for (int off = 8; off >= 1; off >>= 1)
                rs += __shfl_xor_sync(0xffffffffu, rs, off);
            l_i[i] = l_i[i]*alpha + rs;
            m_i[i] = mn;
            accO[i][0] *= alpha;
            accO[i][1] *= alpha;
#pragma unroll
            for (int j = 0; j < 4; j++)
                Ps[ty*4 + i][tx*4 + j] = s[i][j];
        }
        __syncthreads();

#pragma unroll 8
        for (int j = 0; j < 64; j++) {
            float2 v2 = *(const float2*)&Vs[j][tx*2];
#pragma unroll
            for (int i = 0; i < 4; i++) {
                float pv = Ps[ty*4 + i][j];
                accO[i][0] += pv * v2.x;
                accO[i][1] += pv * v2.y;
            }
        }
        __syncthreads();
    }

#pragma unroll
    for (int i = 0; i < 4; i++) {
        int gr = q0 + ty*4 + i;
        if (gr < SS) {
            float inv = 1.f / l_i[i];
            float* dst = g_ctx + (size_t)(b*SS + gr)*DD + h*HDIM + tx*2;
            dst[0] = accO[i][0] * inv;
            dst[1] = accO[i][1] * inv;
        }
    }
}

// ---------------- mean-pool + out-proj ----------------
__global__ void k_pool(const float* __restrict__ Wo, const float* __restrict__ bo,
                       float* __restrict__ out) {
    __shared__ float mean[DD];
    int b = blockIdx.x, t = threadIdx.x;
    float s = 0.f;
    const float* base = g_ctx + (size_t)b*SS*DD + t;
#pragma unroll 8
    for (int si = 0; si < SS; si++) s += base[(size_t)si*DD];
    mean[t] = s * (1.f / (float)SS);
    __syncthreads();
    float acc = bo[t];
    const float* wrow = Wo + t*DD;
#pragma unroll 8
    for (int d = 0; d < DD; d++) acc += mean[d]*wrow[d];
    out[b*DD + t] = acc;
}

// ---------------- launch ----------------
extern "C" void kernel_launch(void* const* d_in, const int* in_sizes, int n_in,
                              void* d_out, int out_size) {
    const float* x    = (const float*)d_in[0];   // (32,1,28,28)
    const float* cw   = (const float*)d_in[1];   // (64,1,9,9)
    const float* emb  = (const float*)d_in[2];   // (64,256)
    const float* ipw  = (const float*)d_in[3];   // (768,256)
    const float* ipb  = (const float*)d_in[4];   // (768)
    const float* opw  = (const float*)d_in[5];   // (256,256)
    const float* opb  = (const float*)d_in[6];   // (256)
    float* out = (float*)d_out;
    int full_out = (out_size >= OUT_FULL) ? 1 : 0;

    k_zero<<<1, 256>>>();
    k_pe<<<SS, 256>>>();
    k_conv<<<dim3(BB, 8), 256>>>(x, cw);
    k_hist1<<<256, 256>>>();
    k_scan<<<1, 256>>>(1);
    k_hist2<<<256, 256>>>();
    k_scan<<<1, 256>>>(2);
    k_hist3<<<256, 256>>>();
    k_scan<<<1, 256>>>(3);
    k_sparse<<<(BB*SS + 255)/256, 256>>>(emb, out, full_out);
    k_qkv0<<<dim3(13, 12), 256>>>(ipw, ipb);
    k_bcast<<<(BB*SS*192)/256, 256>>>();
    k_delta<<<dim3((BB*SS + 63)/64, 12), 256>>>(ipw);
    k_flash<<<dim3(13, NHH, BB), 256>>>();
    k_pool<<<BB, 256>>>(opw, opb, out);
}

// round 4
// speedup vs baseline: 1.6323x; 1.6323x over previous
#include <cuda_runtime.h>
#include <math.h>
#include <stdint.h>

// ---------------- problem constants ----------------
#define BB   32
#define HH   28
#define WW   28
#define C1   64
#define DD   256
#define NHH  8
#define HDIM 32
#define SS   784            // HH*WW
#define TOT  (BB*C1*SS)     // 1,605,632
#define KSEL 803            // ceil(0.0005 * TOT)

#define SW_OFF   8192                      // pooled = 32*256
#define SW_SIZE  (BB*SS*C1)                // 1,605,632
#define IDX_OFF  (SW_OFF + SW_SIZE)        // 1,613,824
#define OUT_FULL (IDX_OFF + BB*SS*2)       // 1,664,000

// ---------------- device scratch ----------------
__device__ __align__(16) float g_A[TOT];                 // conv output (B,C1,S)
__device__ __align__(16) float g_pe[SS*DD];              // positional encoding
__device__ __align__(16) float g_qkv0[SS*3*DD];          // PE @ Wqkv^T + b
__device__ __align__(16) float g_qkv[BB*SS*3*DD];        // per (b,s) qkv
__device__ __align__(16) float g_ctx[BB*SS*DD];          // attention context
__device__ __align__(16) float g_U[BB*SS*DD];            // sparse mix rows (compact)
__device__ int      g_actrow[BB*SS];
__device__ unsigned g_hist1[2048];
__device__ unsigned g_hist2[2048];
__device__ unsigned g_hist3[1024];
__device__ unsigned g_prefix;
__device__ int      g_krem;
__device__ float    g_thresh;
__device__ int      g_nact;

__device__ __forceinline__ float tf32r(float x) {
    uint32_t o;
    asm("cvt.rna.tf32.f32 %0, %1;" : "=r"(o) : "f"(x));
    return __uint_as_float(o);
}
__device__ __forceinline__ void mma_tf32(float c[4], const uint32_t a[4],
                                         uint32_t b0, uint32_t b1) {
    asm volatile("mma.sync.aligned.m16n8k8.row.col.f32.tf32.tf32.f32 "
                 "{%0,%1,%2,%3}, {%4,%5,%6,%7}, {%8,%9}, {%0,%1,%2,%3};"
                 : "+f"(c[0]), "+f"(c[1]), "+f"(c[2]), "+f"(c[3])
                 : "r"(a[0]), "r"(a[1]), "r"(a[2]), "r"(a[3]), "r"(b0), "r"(b1));
}

// ---------------- init: zero hists/counters ----------------
__global__ void k_zero() {
    int t = threadIdx.x;
    for (int i = t; i < 2048; i += 256) { g_hist1[i] = 0; g_hist2[i] = 0; }
    for (int i = t; i < 1024; i += 256) g_hist3[i] = 0;
    if (t == 0) { g_prefix = 0; g_krem = KSEL; g_nact = 0; g_thresh = 0.f; }
}

// ---------------- positional encoding ----------------
__global__ void k_pe() {
    int s = blockIdx.x;            // 0..783
    int d = threadIdx.x;           // 0..255
    int h = s / WW, w = s % WW;
    int i2 = d & ~1;               // even base index (= 2i)
    float div = expf((float)i2 * (-logf(10000.0f) / (float)DD));
    float val = (d & 1) ? cosf((float)w * div) : sinf((float)h * div);
    g_pe[s * DD + d] = val;
}

// ---------------- conv 9x9 + relu (+ fused radix hist level 1) ----------------
__global__ void k_conv(const float* __restrict__ x, const float* __restrict__ cw) {
    __shared__ float xs[36][36];
    __shared__ float ws[8][81];
    __shared__ unsigned sh[2048];
    int b = blockIdx.x, cg = blockIdx.y;
    int t = threadIdx.x;
    for (int e = t; e < 36*36; e += 256) {
        int r = e / 36, c = e % 36;
        int hh = r - 4, ww = c - 4;
        xs[r][c] = (hh >= 0 && hh < HH && ww >= 0 && ww < WW) ? x[b*SS + hh*WW + ww] : 0.f;
    }
    for (int e = t; e < 8*81; e += 256) {
        int c8 = e / 81, k = e % 81;
        ws[c8][k] = cw[(cg*8 + c8)*81 + k];
    }
    for (int i = t; i < 2048; i += 256) sh[i] = 0;
    __syncthreads();
    for (int c8 = 0; c8 < 8; c8++) {
        for (int p = t; p < SS; p += 256) {
            int hh = p / WW, ww = p % WW;
            float acc = 0.f;
#pragma unroll
            for (int ky = 0; ky < 9; ky++)
#pragma unroll
                for (int kx = 0; kx < 9; kx++)
                    acc += xs[hh+ky][ww+kx] * ws[c8][ky*9 + kx];
            acc = fmaxf(acc, 0.f);
            g_A[((b*C1) + cg*8 + c8)*SS + p] = acc;
            unsigned u = __float_as_uint(acc);
            if (u) atomicAdd(&sh[u >> 21], 1u);
        }
    }
    __syncthreads();
    for (int i = t; i < 2048; i += 256) { unsigned v = sh[i]; if (v) atomicAdd(&g_hist1[i], v); }
}

// ---------------- radix-select histograms (levels 2,3) ----------------
__global__ void k_hist2() {
    __shared__ unsigned sh[2048];
    int t = threadIdx.x;
    for (int i = t; i < 2048; i += 256) sh[i] = 0;
    __syncthreads();
    unsigned pf = g_prefix;
    for (int idx = blockIdx.x*256 + t; idx < TOT; idx += gridDim.x*256) {
        unsigned u = __float_as_uint(g_A[idx]);
        if (u && (u >> 21) == pf) atomicAdd(&sh[(u >> 10) & 0x7FF], 1u);
    }
    __syncthreads();
    for (int i = t; i < 2048; i += 256) { unsigned v = sh[i]; if (v) atomicAdd(&g_hist2[i], v); }
}
__global__ void k_hist3() {
    __shared__ unsigned sh[1024];
    int t = threadIdx.x;
    for (int i = t; i < 1024; i += 256) sh[i] = 0;
    __syncthreads();
    unsigned pf = g_prefix;
    for (int idx = blockIdx.x*256 + t; idx < TOT; idx += gridDim.x*256) {
        unsigned u = __float_as_uint(g_A[idx]);
        if (u && (u >> 10) == pf) atomicAdd(&sh[u & 0x3FF], 1u);
    }
    __syncthreads();
    for (int i = t; i < 1024; i += 256) { unsigned v = sh[i]; if (v) atomicAdd(&g_hist3[i], v); }
}

// scan: find bin where suffix-cumulative crosses k
__global__ void k_scan(int level) {
    const unsigned* hist = (level == 1) ? g_hist1 : (level == 2) ? g_hist2 : g_hist3;
    int nbins = (level == 3) ? 1024 : 2048;
    int final_ = (level == 3);
    __shared__ unsigned part[256];
    __shared__ unsigned suf[256];
    int t = threadIdx.x;
    int chunk = nbins / 256;
    unsigned loc[8];
    unsigned psum = 0;
    for (int i = 0; i < chunk; i++) { loc[i] = hist[t*chunk + i]; psum += loc[i]; }
    part[t] = psum; suf[t] = psum;
    __syncthreads();
    for (int off = 1; off < 256; off <<= 1) {
        unsigned v = suf[t];
        if (t + off < 256) v += suf[t + off];
        __syncthreads();
        suf[t] = v;
        __syncthreads();
    }
    unsigned k = (unsigned)g_krem;
    unsigned total = suf[0];
    if (total < k) {
        if (t == 0) { if (final_) g_thresh = 0.f; else g_prefix = 0xFFFFFFFFu; }
        return;
    }
    unsigned above = suf[t] - part[t];
    if (above < k && suf[t] >= k) {
        unsigned cum = above;
        for (int i = chunk - 1; i >= 0; i--) {
            cum += loc[i];
            if (cum >= k) {
                unsigned sel = (unsigned)(t*chunk + i);
                if (final_) g_thresh = __uint_as_float((g_prefix << 10) | sel);
                else { g_prefix = (g_prefix << 11) | sel; g_krem = (int)(k - (cum - loc[i])); }
                break;
            }
        }
    }
}

// ---------------- per-pixel sparse softmax + outputs + compact U ----------------
__global__ void k_sparse(const float* __restrict__ emb, float* __restrict__ out, int full_out) {
    int p = blockIdx.x*256 + threadIdx.x;
    if (p >= BB*SS) return;
    int b = p / SS, s = p % SS;
    float thr = g_thresh;
    float m1 = -INFINITY, m2 = -INFINITY;
    int i1 = 0, i2 = 0, cnt = 0;
    const float* ap = g_A + (size_t)b*C1*SS + s;
#pragma unroll 8
    for (int c = 0; c < C1; c++) {
        float a = ap[c*SS];
        float v = (a >= thr) ? a : 0.f;
        if (v > 0.f) cnt++;
        if (v > m1) { m2 = m1; i2 = i1; m1 = v; i1 = c; }
        else if (v > m2) { m2 = v; i2 = c; }
    }
    float wA = 0.f, wB = 0.f;
    if (cnt == 1) wA = 1.f;
    else if (cnt >= 2) {
        float e2 = expf(m2 - m1);
        float z = 1.f + e2;
        wA = 1.f / z; wB = e2 / z;
    }
    if (full_out) {
        float* sw = out + SW_OFF + (size_t)p*C1;
        for (int c = 0; c < C1; c++) {
            float o = 0.f;
            if (c == i1) o = wA; else if (c == i2) o = wB;
            sw[c] = o;
        }
        out[IDX_OFF + p*2]     = (float)i1;
        out[IDX_OFF + p*2 + 1] = (float)i2;
    }
    if (cnt > 0) {
        int slot = atomicAdd(&g_nact, 1);
        g_actrow[slot] = p;
        float w2v = (cnt >= 2) ? wB : 0.f;
        float* up = g_U + (size_t)slot*DD;
        const float* e1p = emb + i1*DD;
        const float* e2p = emb + i2*DD;
        for (int d = 0; d < DD; d++) up[d] = wA*e1p[d] + w2v*e2p[d];
    }
}

// ---------------- qkv0 = PE @ Wqkv^T + b ----------------
__global__ void k_qkv0(const float* __restrict__ Wq, const float* __restrict__ bias) {
    __shared__ float As[16][68];
    __shared__ float Bs[16][68];
    int tx = threadIdx.x % 16, ty = threadIdx.x / 16;
    int m0 = blockIdx.x*64, n0 = blockIdx.y*64;
    float acc[4][4] = {};
    int lr = threadIdx.x / 4;
    int lk = (threadIdx.x % 4) * 4;
    for (int k0 = 0; k0 < DD; k0 += 16) {
        float4 av = (m0 + lr < SS) ? *(const float4*)&g_pe[(m0+lr)*DD + k0 + lk] : make_float4(0,0,0,0);
        float4 bv = *(const float4*)&Wq[(n0+lr)*DD + k0 + lk];
        __syncthreads();
        As[lk+0][lr] = av.x; As[lk+1][lr] = av.y; As[lk+2][lr] = av.z; As[lk+3][lr] = av.w;
        Bs[lk+0][lr] = bv.x; Bs[lk+1][lr] = bv.y; Bs[lk+2][lr] = bv.z; Bs[lk+3][lr] = bv.w;
        __syncthreads();
#pragma unroll
        for (int kk = 0; kk < 16; kk++) {
            float4 a4 = *(const float4*)&As[kk][ty*4];
            float4 b4 = *(const float4*)&Bs[kk][tx*4];
            float sa[4] = {a4.x, a4.y, a4.z, a4.w};
            float sb[4] = {b4.x, b4.y, b4.z, b4.w};
#pragma unroll
            for (int i = 0; i < 4; i++)
#pragma unroll
                for (int j = 0; j < 4; j++)
                    acc[i][j] += sa[i]*sb[j];
        }
    }
#pragma unroll
    for (int i = 0; i < 4; i++) {
        int m = m0 + ty*4 + i;
        if (m < SS)
#pragma unroll
            for (int j = 0; j < 4; j++) {
                int n = n0 + tx*4 + j;
                g_qkv0[m*768 + n] = acc[i][j] + bias[n];
            }
    }
}

// ---------------- broadcast qkv0 to all batches ----------------
__global__ void k_bcast() {
    int idx = blockIdx.x*256 + threadIdx.x;
    int n4 = idx % 192;
    int bsrow = idx / 192;
    int s = bsrow % SS;
    const float4* src = (const float4*)g_qkv0;
    float4* dst = (float4*)g_qkv;
    dst[idx] = src[s*192 + n4];
}

// ---------------- delta = U @ Wqkv^T, scatter-add into qkv ----------------
__global__ void k_delta(const float* __restrict__ Wq) {
    int nact = g_nact;
    int m0 = blockIdx.x*64;
    if (m0 >= nact) return;
    __shared__ float As[16][68];
    __shared__ float Bs[16][68];
    int tx = threadIdx.x % 16, ty = threadIdx.x / 16;
    int n0 = blockIdx.y*64;
    float acc[4][4] = {};
    int lr = threadIdx.x / 4;
    int lk = (threadIdx.x % 4) * 4;
    for (int k0 = 0; k0 < DD; k0 += 16) {
        float4 av = (m0 + lr < nact) ? *(const float4*)&g_U[(size_t)(m0+lr)*DD + k0 + lk] : make_float4(0,0,0,0);
        float4 bv = *(const float4*)&Wq[(n0+lr)*DD + k0 + lk];
        __syncthreads();
        As[lk+0][lr] = av.x; As[lk+1][lr] = av.y; As[lk+2][lr] = av.z; As[lk+3][lr] = av.w;
        Bs[lk+0][lr] = bv.x; Bs[lk+1][lr] = bv.y; Bs[lk+2][lr] = bv.z; Bs[lk+3][lr] = bv.w;
        __syncthreads();
#pragma unroll
        for (int kk = 0; kk < 16; kk++) {
            float4 a4 = *(const float4*)&As[kk][ty*4];
            float4 b4 = *(const float4*)&Bs[kk][tx*4];
            float sa[4] = {a4.x, a4.y, a4.z, a4.w};
            float sb[4] = {b4.x, b4.y, b4.z, b4.w};
#pragma unroll
            for (int i = 0; i < 4; i++)
#pragma unroll
                for (int j = 0; j < 4; j++)
                    acc[i][j] += sa[i]*sb[j];
        }
    }
#pragma unroll
    for (int i = 0; i < 4; i++) {
        int m = m0 + ty*4 + i;
        if (m < nact) {
            int p = g_actrow[m];
            float* dst = g_qkv + (size_t)p*768 + n0 + tx*4;
#pragma unroll
            for (int j = 0; j < 4; j++) dst[j] += acc[i][j];
        }
    }
}

// ---------------- tensor-core flash attention (3xTF32 QK, tf32 PV) ----------------
// 128 threads / 4 warps, each warp owns 16 q-rows (one m16 tile).
// Q hi/lo fragments in registers; K hi/lo in smem; P staged via QP buffer
// (width 68 >= 64 cols!). smem = 17408 + 9216 + 9216 + 10240 = 46080 < 48KB.
#define FM 64
#define FN 64
__global__ __launch_bounds__(128) void k_flash() {
    __shared__ __align__(16) float QP[FM][68];    // Q staging (cols 0..31), then P (cols 0..63)
    __shared__ __align__(16) float Kh[FN][36];
    __shared__ __align__(16) float Kl[FN][36];
    __shared__ __align__(16) float Vs[FN][40];
    int b = blockIdx.z, h = blockIdx.y;
    int q0 = blockIdx.x * FM;
    int t = threadIdx.x;
    int w = t >> 5, lane = t & 31;
    int l4 = lane >> 2, lm = lane & 3;
    const float scale = 0.17677669529663689f;

    const float* qbase = g_qkv + (size_t)b*SS*768;

    // stage scaled fp32 Q
    for (int f = t; f < FM*8; f += 128) {
        int r = f >> 3, c4 = (f & 7) * 4;
        int gr = q0 + r;
        float4 v = (gr < SS) ? *(const float4*)(qbase + (size_t)gr*768 + h*HDIM + c4)
                             : make_float4(0.f,0.f,0.f,0.f);
        QP[r][c4+0] = v.x*scale; QP[r][c4+1] = v.y*scale;
        QP[r][c4+2] = v.z*scale; QP[r][c4+3] = v.w*scale;
    }
    __syncthreads();

    int r0 = w * 16;
    // hoist Q hi/lo fragments: [ks][4]
    uint32_t aqh[4][4], aql[4][4];
#pragma unroll
    for (int ks = 0; ks < 4; ks++) {
        int kk = ks*8;
        float v[4];
        v[0] = QP[r0+l4  ][kk+lm  ];
        v[1] = QP[r0+l4+8][kk+lm  ];
        v[2] = QP[r0+l4  ][kk+lm+4];
        v[3] = QP[r0+l4+8][kk+lm+4];
#pragma unroll
        for (int j = 0; j < 4; j++) {
            float hi = tf32r(v[j]);
            aqh[ks][j] = __float_as_uint(hi);
            aql[ks][j] = __float_as_uint(tf32r(v[j] - hi));
        }
    }
    // from here warp w uses only QP rows [r0, r0+16) as its private P tile.

    float m_i[2], l_i[2], o[4][4];
#pragma unroll
    for (int hf = 0; hf < 2; hf++) { m_i[hf] = -INFINITY; l_i[hf] = 0.f; }
#pragma unroll
    for (int nt = 0; nt < 4; nt++)
#pragma unroll
        for (int c = 0; c < 4; c++) o[nt][c] = 0.f;

    for (int k0 = 0; k0 < SS; k0 += FN) {
        __syncthreads();   // protect Kh/Kl/Vs reuse
        for (int f = t; f < FN*8; f += 128) {
            int r = f >> 3, c4 = (f & 7) * 4;
            int gr = k0 + r;
            float4 kv = make_float4(0.f,0.f,0.f,0.f), vv = make_float4(0.f,0.f,0.f,0.f);
            if (gr < SS) {
                const float* base = qbase + (size_t)gr*768 + h*HDIM + c4;
                kv = *(const float4*)(base + DD);
                vv = *(const float4*)(base + 2*DD);
            }
            float kh0 = tf32r(kv.x), kh1 = tf32r(kv.y), kh2 = tf32r(kv.z), kh3 = tf32r(kv.w);
            Kh[r][c4+0] = kh0; Kh[r][c4+1] = kh1; Kh[r][c4+2] = kh2; Kh[r][c4+3] = kh3;
            Kl[r][c4+0] = tf32r(kv.x - kh0); Kl[r][c4+1] = tf32r(kv.y - kh1);
            Kl[r][c4+2] = tf32r(kv.z - kh2); Kl[r][c4+3] = tf32r(kv.w - kh3);
            Vs[r][c4+0] = tf32r(vv.x); Vs[r][c4+1] = tf32r(vv.y);
            Vs[r][c4+2] = tf32r(vv.z); Vs[r][c4+3] = tf32r(vv.w);
        }
        __syncthreads();

        float c[8][4];
#pragma unroll
        for (int nt = 0; nt < 8; nt++) {
            c[nt][0] = c[nt][1] = c[nt][2] = c[nt][3] = 0.f;
#pragma unroll
            for (int ks = 0; ks < 4; ks++) {
                int kk = ks*8;
                int kr = nt*8 + l4;
                uint32_t bh0 = __float_as_uint(Kh[kr][kk+lm  ]);
                uint32_t bh1 = __float_as_uint(Kh[kr][kk+lm+4]);
                uint32_t bl0 = __float_as_uint(Kl[kr][kk+lm  ]);
                uint32_t bl1 = __float_as_uint(Kl[kr][kk+lm+4]);
                mma_tf32(c[nt], aqh[ks], bl0, bl1);   // Qh*Kl
                mma_tf32(c[nt], aql[ks], bh0, bh1);   // Ql*Kh
                mma_tf32(c[nt], aqh[ks], bh0, bh1);   // Qh*Kh (last: dominant term)
            }
        }
        if (k0 + FN > SS) {
#pragma unroll
            for (int nt = 0; nt < 8; nt++) {
                int j0 = k0 + nt*8 + lm*2;
                if (j0 >= SS) { c[nt][0] = c[nt][1] = c[nt][2] = c[nt][3] = -1e30f; }
            }
        }
#pragma unroll
        for (int hf = 0; hf < 2; hf++) {
            float rm = -INFINITY;
#pragma unroll
            for (int nt = 0; nt < 8; nt++)
                rm = fmaxf(rm, fmaxf(c[nt][2*hf], c[nt][2*hf+1]));
            rm = fmaxf(rm, __shfl_xor_sync(0xffffffffu, rm, 1));
            rm = fmaxf(rm, __shfl_xor_sync(0xffffffffu, rm, 2));
            float mn = fmaxf(m_i[hf], rm);
            float alpha = __expf(m_i[hf] - mn);
            float rs = 0.f;
#pragma unroll
            for (int nt = 0; nt < 8; nt++) {
                float p0 = __expf(c[nt][2*hf]   - mn);
                float p1 = __expf(c[nt][2*hf+1] - mn);
                c[nt][2*hf] = p0; c[nt][2*hf+1] = p1;
                rs += p0 + p1;
            }
            rs += __shfl_xor_sync(0xffffffffu, rs, 1);
            rs += __shfl_xor_sync(0xffffffffu, rs, 2);
            l_i[hf] = l_i[hf]*alpha + rs;
            m_i[hf] = mn;
#pragma unroll
            for (int nt = 0; nt < 4; nt++) {
                o[nt][2*hf]   *= alpha;
                o[nt][2*hf+1] *= alpha;
            }
        }
        // stage P (tf32) into per-warp rows of QP (width 68 — fits 64 cols)
#pragma unroll
        for (int nt = 0; nt < 8; nt++) {
            *(float2*)&QP[r0+l4  ][nt*8+lm*2] = make_float2(tf32r(c[nt][0]), tf32r(c[nt][1]));
            *(float2*)&QP[r0+l4+8][nt*8+lm*2] = make_float2(tf32r(c[nt][2]), tf32r(c[nt][3]));
        }
        __syncwarp();
        // PV: o += P @ V
#pragma unroll
        for (int ks = 0; ks < 8; ks++) {
            int kk = ks*8;
            uint32_t a[4];
            a[0] = __float_as_uint(QP[r0+l4  ][kk+lm  ]);
            a[1] = __float_as_uint(QP[r0+l4+8][kk+lm  ]);
            a[2] = __float_as_uint(QP[r0+l4  ][kk+lm+4]);
            a[3] = __float_as_uint(QP[r0+l4+8][kk+lm+4]);
#pragma unroll
            for (int nt = 0; nt < 4; nt++) {
                uint32_t b0 = __float_as_uint(Vs[kk+lm  ][nt*8+l4]);
                uint32_t b1 = __float_as_uint(Vs[kk+lm+4][nt*8+l4]);
                mma_tf32(o[nt], a, b0, b1);
            }
        }
        __syncwarp();   // P reads done before next chunk overwrites (same warp rows; safe anyway)
    }

#pragma unroll
    for (int hf = 0; hf < 2; hf++) {
        int gr = q0 + r0 + l4 + hf*8;
        if (gr < SS) {
            float inv = 1.f / l_i[hf];
#pragma unroll
            for (int nt = 0; nt < 4; nt++) {
                float2 v = make_float2(o[nt][2*hf]*inv, o[nt][2*hf+1]*inv);
                *(float2*)&g_ctx[(size_t)(b*SS+gr)*DD + h*HDIM + nt*8 + lm*2] = v;
            }
        }
    }
}

// ---------------- mean-pool + out-proj ----------------
__global__ void k_pool(const float* __restrict__ Wo, const float* __restrict__ bo,
                       float* __restrict__ out) {
    __shared__ float mean[DD];
    int b = blockIdx.x, t = threadIdx.x;
    float s = 0.f;
    const float* base = g_ctx + (size_t)b*SS*DD + t;
#pragma unroll 8
    for (int si = 0; si < SS; si++) s += base[(size_t)si*DD];
    mean[t] = s * (1.f / (float)SS);
    __syncthreads();
    float acc = bo[t];
    const float* wrow = Wo + t*DD;
#pragma unroll 8
    for (int d = 0; d < DD; d++) acc += mean[d]*wrow[d];
    out[b*DD + t] = acc;
}

// ---------------- launch ----------------
extern "C" void kernel_launch(void* const* d_in, const int* in_sizes, int n_in,
                              void* d_out, int out_size) {
    const float* x    = (const float*)d_in[0];
    const float* cw   = (const float*)d_in[1];
    const float* emb  = (const float*)d_in[2];
    const float* ipw  = (const float*)d_in[3];
    const float* ipb  = (const float*)d_in[4];
    const float* opw  = (const float*)d_in[5];
    const float* opb  = (const float*)d_in[6];
    float* out = (float*)d_out;
    int full_out = (out_size >= OUT_FULL) ? 1 : 0;

    k_zero<<<1, 256>>>();
    k_pe<<<SS, 256>>>();
    k_conv<<<dim3(BB, 8), 256>>>(x, cw);
    k_scan<<<1, 256>>>(1);
    k_hist2<<<256, 256>>>();
    k_scan<<<1, 256>>>(2);
    k_hist3<<<256, 256>>>();
    k_scan<<<1, 256>>>(3);
    k_sparse<<<(BB*SS + 255)/256, 256>>>(emb, out, full_out);
    k_qkv0<<<dim3(13, 12), 256>>>(ipw, ipb);
    k_bcast<<<(BB*SS*192)/256, 256>>>();
    k_delta<<<dim3((BB*SS + 63)/64, 12), 256>>>(ipw);
    k_flash<<<dim3((SS + FM - 1)/FM, NHH, BB), 128>>>();
    k_pool<<<BB, 256>>>(opw, opb, out);
}

// round 5
// speedup vs baseline: 1.6482x; 1.0098x over previous
#include <cuda_runtime.h>
#include <math.h>
#include <stdint.h>

// ---------------- problem constants ----------------
#define BB   32
#define HH   28
#define WW   28
#define C1   64
#define DD   256
#define NHH  8
#define HDIM 32
#define SS   784            // HH*WW
#define TOT  (BB*C1*SS)     // 1,605,632
#define KSEL 803            // ceil(0.0005 * TOT)
#define MAXACT 832          // >= KSEL, padded to 64

#define SW_OFF   8192                      // pooled = 32*256
#define SW_SIZE  (BB*SS*C1)                // 1,605,632
#define IDX_OFF  (SW_OFF + SW_SIZE)        // 1,613,824
#define OUT_FULL (IDX_OFF + BB*SS*2)       // 1,664,000

// ---------------- device scratch ----------------
__device__ __align__(16) float g_A[TOT];                 // conv output (B,C1,S)
__device__ __align__(16) float g_pe[SS*DD];              // positional encoding
__device__ __align__(16) float g_qkv0[SS*3*DD];          // PE @ Wqkv^T + b  (batch-invariant)
__device__ __align__(16) float g_dq[MAXACT*3*DD];        // sparse qkv deltas (compact)
__device__ __align__(16) float g_ctx[BB*SS*DD];          // attention context
__device__ __align__(16) float g_U[MAXACT*DD];           // sparse mix rows (compact)
__device__ int      g_didx[BB*SS];                       // (b,s) -> slot or -1
__device__ int      g_actrow[MAXACT];
__device__ unsigned g_hist1[2048];
__device__ unsigned g_hist2[2048];
__device__ unsigned g_hist3[1024];
__device__ unsigned g_prefix;
__device__ int      g_krem;
__device__ float    g_thresh;
__device__ int      g_nact;

__device__ __forceinline__ float tf32r(float x) {
    uint32_t o;
    asm("cvt.rna.tf32.f32 %0, %1;" : "=r"(o) : "f"(x));
    return __uint_as_float(o);
}
__device__ __forceinline__ void mma_tf32(float c[4], const uint32_t a[4],
                                         uint32_t b0, uint32_t b1) {
    asm volatile("mma.sync.aligned.m16n8k8.row.col.f32.tf32.tf32.f32 "
                 "{%0,%1,%2,%3}, {%4,%5,%6,%7}, {%8,%9}, {%0,%1,%2,%3};"
                 : "+f"(c[0]), "+f"(c[1]), "+f"(c[2]), "+f"(c[3])
                 : "r"(a[0]), "r"(a[1]), "r"(a[2]), "r"(a[3]), "r"(b0), "r"(b1));
}

// ---------------- positional encoding (+ global init in block 0) ----------------
__global__ void k_pe() {
    int s = blockIdx.x;            // 0..783
    int d = threadIdx.x;           // 0..255
    if (s == 0) {
        for (int i = d; i < 2048; i += 256) { g_hist1[i] = 0; g_hist2[i] = 0; }
        for (int i = d; i < 1024; i += 256) g_hist3[i] = 0;
        if (d == 0) { g_prefix = 0; g_krem = KSEL; g_nact = 0; g_thresh = 0.f; }
    }
    int h = s / WW, w = s % WW;
    int i2 = d & ~1;               // even base index (= 2i)
    float div = expf((float)i2 * (-logf(10000.0f) / (float)DD));
    float val = (d & 1) ? cosf((float)w * div) : sinf((float)h * div);
    g_pe[s * DD + d] = val;
}

// ---------------- conv 9x9 + relu (+ fused radix hist level 1) ----------------
__global__ void k_conv(const float* __restrict__ x, const float* __restrict__ cw) {
    __shared__ float xs[36][36];
    __shared__ float ws[8][81];
    __shared__ unsigned sh[2048];
    int b = blockIdx.x, cg = blockIdx.y;
    int t = threadIdx.x;
    for (int e = t; e < 36*36; e += 256) {
        int r = e / 36, c = e % 36;
        int hh = r - 4, ww = c - 4;
        xs[r][c] = (hh >= 0 && hh < HH && ww >= 0 && ww < WW) ? x[b*SS + hh*WW + ww] : 0.f;
    }
    for (int e = t; e < 8*81; e += 256) {
        int c8 = e / 81, k = e % 81;
        ws[c8][k] = cw[(cg*8 + c8)*81 + k];
    }
    for (int i = t; i < 2048; i += 256) sh[i] = 0;
    __syncthreads();
    for (int c8 = 0; c8 < 8; c8++) {
        for (int p = t; p < SS; p += 256) {
            int hh = p / WW, ww = p % WW;
            float acc = 0.f;
#pragma unroll
            for (int ky = 0; ky < 9; ky++)
#pragma unroll
                for (int kx = 0; kx < 9; kx++)
                    acc += xs[hh+ky][ww+kx] * ws[c8][ky*9 + kx];
            acc = fmaxf(acc, 0.f);
            g_A[((b*C1) + cg*8 + c8)*SS + p] = acc;
            unsigned u = __float_as_uint(acc);
            if (u) atomicAdd(&sh[u >> 21], 1u);
        }
    }
    __syncthreads();
    for (int i = t; i < 2048; i += 256) { unsigned v = sh[i]; if (v) atomicAdd(&g_hist1[i], v); }
}

// ---------------- radix-select histograms (levels 2,3) ----------------
__global__ void k_hist2() {
    __shared__ unsigned sh[2048];
    int t = threadIdx.x;
    for (int i = t; i < 2048; i += 256) sh[i] = 0;
    __syncthreads();
    unsigned pf = g_prefix;
    for (int idx = blockIdx.x*256 + t; idx < TOT; idx += gridDim.x*256) {
        unsigned u = __float_as_uint(g_A[idx]);
        if (u && (u >> 21) == pf) atomicAdd(&sh[(u >> 10) & 0x7FF], 1u);
    }
    __syncthreads();
    for (int i = t; i < 2048; i += 256) { unsigned v = sh[i]; if (v) atomicAdd(&g_hist2[i], v); }
}
__global__ void k_hist3() {
    __shared__ unsigned sh[1024];
    int t = threadIdx.x;
    for (int i = t; i < 1024; i += 256) sh[i] = 0;
    __syncthreads();
    unsigned pf = g_prefix;
    for (int idx = blockIdx.x*256 + t; idx < TOT; idx += gridDim.x*256) {
        unsigned u = __float_as_uint(g_A[idx]);
        if (u && (u >> 10) == pf) atomicAdd(&sh[u & 0x3FF], 1u);
    }
    __syncthreads();
    for (int i = t; i < 1024; i += 256) { unsigned v = sh[i]; if (v) atomicAdd(&g_hist3[i], v); }
}

// scan: find bin where suffix-cumulative crosses k
__global__ void k_scan(int level) {
    const unsigned* hist = (level == 1) ? g_hist1 : (level == 2) ? g_hist2 : g_hist3;
    int nbins = (level == 3) ? 1024 : 2048;
    int final_ = (level == 3);
    __shared__ unsigned part[256];
    __shared__ unsigned suf[256];
    int t = threadIdx.x;
    int chunk = nbins / 256;
    unsigned loc[8];
    unsigned psum = 0;
    for (int i = 0; i < chunk; i++) { loc[i] = hist[t*chunk + i]; psum += loc[i]; }
    part[t] = psum; suf[t] = psum;
    __syncthreads();
    for (int off = 1; off < 256; off <<= 1) {
        unsigned v = suf[t];
        if (t + off < 256) v += suf[t + off];
        __syncthreads();
        suf[t] = v;
        __syncthreads();
    }
    unsigned k = (unsigned)g_krem;
    unsigned total = suf[0];
    if (total < k) {
        if (t == 0) { if (final_) g_thresh = 0.f; else g_prefix = 0xFFFFFFFFu; }
        return;
    }
    unsigned above = suf[t] - part[t];
    if (above < k && suf[t] >= k) {
        unsigned cum = above;
        for (int i = chunk - 1; i >= 0; i--) {
            cum += loc[i];
            if (cum >= k) {
                unsigned sel = (unsigned)(t*chunk + i);
                if (final_) g_thresh = __uint_as_float((g_prefix << 10) | sel);
                else { g_prefix = (g_prefix << 11) | sel; g_krem = (int)(k - (cum - loc[i])); }
                break;
            }
        }
    }
}

// ---------------- per-pixel sparse softmax + outputs + compact U + didx ----------------
__global__ void k_sparse(const float* __restrict__ emb, float* __restrict__ out, int full_out) {
    int p = blockIdx.x*256 + threadIdx.x;
    if (p >= BB*SS) return;
    int b = p / SS, s = p % SS;
    float thr = g_thresh;
    float m1 = -INFINITY, m2 = -INFINITY;
    int i1 = 0, i2 = 0, cnt = 0;
    const float* ap = g_A + (size_t)b*C1*SS + s;
#pragma unroll 8
    for (int c = 0; c < C1; c++) {
        float a = ap[c*SS];
        float v = (a >= thr) ? a : 0.f;
        if (v > 0.f) cnt++;
        if (v > m1) { m2 = m1; i2 = i1; m1 = v; i1 = c; }
        else if (v > m2) { m2 = v; i2 = c; }
    }
    float wA = 0.f, wB = 0.f;
    if (cnt == 1) wA = 1.f;
    else if (cnt >= 2) {
        float e2 = expf(m2 - m1);
        float z = 1.f + e2;
        wA = 1.f / z; wB = e2 / z;
    }
    if (full_out) {
        float* sw = out + SW_OFF + (size_t)p*C1;
        for (int c = 0; c < C1; c++) {
            float o = 0.f;
            if (c == i1) o = wA; else if (c == i2) o = wB;
            sw[c] = o;
        }
        out[IDX_OFF + p*2]     = (float)i1;
        out[IDX_OFF + p*2 + 1] = (float)i2;
    }
    int slotw = -1;
    if (cnt > 0) {
        int slot = atomicAdd(&g_nact, 1);
        if (slot < MAXACT) {
            slotw = slot;
            g_actrow[slot] = p;
            float w2v = (cnt >= 2) ? wB : 0.f;
            float* up = g_U + (size_t)slot*DD;
            const float* e1p = emb + i1*DD;
            const float* e2p = emb + i2*DD;
            for (int d = 0; d < DD; d++) up[d] = wA*e1p[d] + w2v*e2p[d];
        }
    }
    g_didx[p] = slotw;
}

// ---------------- qkv0 = PE @ Wqkv^T + b ----------------
__global__ void k_qkv0(const float* __restrict__ Wq, const float* __restrict__ bias) {
    __shared__ float As[16][68];
    __shared__ float Bs[16][68];
    int tx = threadIdx.x % 16, ty = threadIdx.x / 16;
    int m0 = blockIdx.x*64, n0 = blockIdx.y*64;
    float acc[4][4] = {};
    int lr = threadIdx.x / 4;
    int lk = (threadIdx.x % 4) * 4;
    for (int k0 = 0; k0 < DD; k0 += 16) {
        float4 av = (m0 + lr < SS) ? *(const float4*)&g_pe[(m0+lr)*DD + k0 + lk] : make_float4(0,0,0,0);
        float4 bv = *(const float4*)&Wq[(n0+lr)*DD + k0 + lk];
        __syncthreads();
        As[lk+0][lr] = av.x; As[lk+1][lr] = av.y; As[lk+2][lr] = av.z; As[lk+3][lr] = av.w;
        Bs[lk+0][lr] = bv.x; Bs[lk+1][lr] = bv.y; Bs[lk+2][lr] = bv.z; Bs[lk+3][lr] = bv.w;
        __syncthreads();
#pragma unroll
        for (int kk = 0; kk < 16; kk++) {
            float4 a4 = *(const float4*)&As[kk][ty*4];
            float4 b4 = *(const float4*)&Bs[kk][tx*4];
            float sa[4] = {a4.x, a4.y, a4.z, a4.w};
            float sb[4] = {b4.x, b4.y, b4.z, b4.w};
#pragma unroll
            for (int i = 0; i < 4; i++)
#pragma unroll
                for (int j = 0; j < 4; j++)
                    acc[i][j] += sa[i]*sb[j];
        }
    }
#pragma unroll
    for (int i = 0; i < 4; i++) {
        int m = m0 + ty*4 + i;
        if (m < SS)
#pragma unroll
            for (int j = 0; j < 4; j++) {
                int n = n0 + tx*4 + j;
                g_qkv0[m*768 + n] = acc[i][j] + bias[n];
            }
    }
}

// ---------------- dq = U @ Wqkv^T (compact rows, no bias) ----------------
__global__ void k_delta(const float* __restrict__ Wq) {
    int nact = g_nact; if (nact > MAXACT) nact = MAXACT;
    int m0 = blockIdx.x*64;
    if (m0 >= nact) return;
    __shared__ float As[16][68];
    __shared__ float Bs[16][68];
    int tx = threadIdx.x % 16, ty = threadIdx.x / 16;
    int n0 = blockIdx.y*64;
    float acc[4][4] = {};
    int lr = threadIdx.x / 4;
    int lk = (threadIdx.x % 4) * 4;
    for (int k0 = 0; k0 < DD; k0 += 16) {
        float4 av = (m0 + lr < nact) ? *(const float4*)&g_U[(size_t)(m0+lr)*DD + k0 + lk] : make_float4(0,0,0,0);
        float4 bv = *(const float4*)&Wq[(n0+lr)*DD + k0 + lk];
        __syncthreads();
        As[lk+0][lr] = av.x; As[lk+1][lr] = av.y; As[lk+2][lr] = av.z; As[lk+3][lr] = av.w;
        Bs[lk+0][lr] = bv.x; Bs[lk+1][lr] = bv.y; Bs[lk+2][lr] = bv.z; Bs[lk+3][lr] = bv.w;
        __syncthreads();
#pragma unroll
        for (int kk = 0; kk < 16; kk++) {
            float4 a4 = *(const float4*)&As[kk][ty*4];
            float4 b4 = *(const float4*)&Bs[kk][tx*4];
            float sa[4] = {a4.x, a4.y, a4.z, a4.w};
            float sb[4] = {b4.x, b4.y, b4.z, b4.w};
#pragma unroll
            for (int i = 0; i < 4; i++)
#pragma unroll
                for (int j = 0; j < 4; j++)
                    acc[i][j] += sa[i]*sb[j];
        }
    }
#pragma unroll
    for (int i = 0; i < 4; i++) {
        int m = m0 + ty*4 + i;
        if (m < nact) {
            float* dst = g_dq + (size_t)m*768 + n0 + tx*4;
#pragma unroll
            for (int j = 0; j < 4; j++) dst[j] = acc[i][j];
        }
    }
}

// ---------------- tensor-core flash attention (3xTF32 QK, tf32 PV) ----------------
// Sources: qkv0 (L2-resident, batch-shared) + sparse dq via didx.
// smem = QP 17408 + Ks 9216 + Vs 10240 = 36864 bytes.
#define FM 64
#define FN 64
__global__ __launch_bounds__(128) void k_flash() {
    __shared__ __align__(16) float QP[FM][68];    // Q staging (cols 0..31), then P (cols 0..63)
    __shared__ __align__(16) float Ks[FN][36];    // raw fp32 K (hi/lo split at fragment load)
    __shared__ __align__(16) float Vs[FN][40];    // tf32-rounded V
    int b = blockIdx.z, h = blockIdx.y;
    int q0 = blockIdx.x * FM;
    int t = threadIdx.x;
    int w = t >> 5, lane = t & 31;
    int l4 = lane >> 2, lm = lane & 3;
    const float scale = 0.17677669529663689f;

    const int* didx = g_didx + b*SS;

    // stage scaled fp32 Q (= qkv0 + dq)
    for (int f = t; f < FM*8; f += 128) {
        int r = f >> 3, c4 = (f & 7) * 4;
        int gr = q0 + r;
        float4 v = make_float4(0.f,0.f,0.f,0.f);
        if (gr < SS) {
            v = *(const float4*)(g_qkv0 + (size_t)gr*768 + h*HDIM + c4);
            int sl = didx[gr];
            if (sl >= 0) {
                float4 d = *(const float4*)(g_dq + (size_t)sl*768 + h*HDIM + c4);
                v.x += d.x; v.y += d.y; v.z += d.z; v.w += d.w;
            }
        }
        QP[r][c4+0] = v.x*scale; QP[r][c4+1] = v.y*scale;
        QP[r][c4+2] = v.z*scale; QP[r][c4+3] = v.w*scale;
    }
    __syncthreads();

    int r0 = w * 16;
    // hoist Q hi/lo fragments: [ks][4]
    uint32_t aqh[4][4], aql[4][4];
#pragma unroll
    for (int ks = 0; ks < 4; ks++) {
        int kk = ks*8;
        float v[4];
        v[0] = QP[r0+l4  ][kk+lm  ];
        v[1] = QP[r0+l4+8][kk+lm  ];
        v[2] = QP[r0+l4  ][kk+lm+4];
        v[3] = QP[r0+l4+8][kk+lm+4];
#pragma unroll
        for (int j = 0; j < 4; j++) {
            float hi = tf32r(v[j]);
            aqh[ks][j] = __float_as_uint(hi);
            aql[ks][j] = __float_as_uint(tf32r(v[j] - hi));
        }
    }
    // from here warp w uses only QP rows [r0, r0+16) as its private P tile.

    float m_i[2], l_i[2], o[4][4];
#pragma unroll
    for (int hf = 0; hf < 2; hf++) { m_i[hf] = -INFINITY; l_i[hf] = 0.f; }
#pragma unroll
    for (int nt = 0; nt < 4; nt++)
#pragma unroll
        for (int c = 0; c < 4; c++) o[nt][c] = 0.f;

    for (int k0 = 0; k0 < SS; k0 += FN) {
        __syncthreads();   // protect Ks/Vs reuse
        for (int f = t; f < FN*8; f += 128) {
            int r = f >> 3, c4 = (f & 7) * 4;
            int gr = k0 + r;
            float4 kv = make_float4(0.f,0.f,0.f,0.f), vv = make_float4(0.f,0.f,0.f,0.f);
            if (gr < SS) {
                const float* base = g_qkv0 + (size_t)gr*768 + h*HDIM + c4;
                kv = *(const float4*)(base + DD);
                vv = *(const float4*)(base + 2*DD);
                int sl = didx[gr];
                if (sl >= 0) {
                    const float* dbase = g_dq + (size_t)sl*768 + h*HDIM + c4;
                    float4 dk = *(const float4*)(dbase + DD);
                    float4 dv = *(const float4*)(dbase + 2*DD);
                    kv.x += dk.x; kv.y += dk.y; kv.z += dk.z; kv.w += dk.w;
                    vv.x += dv.x; vv.y += dv.y; vv.z += dv.z; vv.w += dv.w;
                }
            }
            Ks[r][c4+0] = kv.x; Ks[r][c4+1] = kv.y; Ks[r][c4+2] = kv.z; Ks[r][c4+3] = kv.w;
            Vs[r][c4+0] = tf32r(vv.x); Vs[r][c4+1] = tf32r(vv.y);
            Vs[r][c4+2] = tf32r(vv.z); Vs[r][c4+3] = tf32r(vv.w);
        }
        __syncthreads();

        float c[8][4];
#pragma unroll
        for (int nt = 0; nt < 8; nt++) {
            c[nt][0] = c[nt][1] = c[nt][2] = c[nt][3] = 0.f;
#pragma unroll
            for (int ks = 0; ks < 4; ks++) {
                int kk = ks*8;
                int kr = nt*8 + l4;
                float k0f = Ks[kr][kk+lm  ];
                float k1f = Ks[kr][kk+lm+4];
                float h0 = tf32r(k0f), h1 = tf32r(k1f);
                uint32_t bh0 = __float_as_uint(h0);
                uint32_t bh1 = __float_as_uint(h1);
                uint32_t bl0 = __float_as_uint(tf32r(k0f - h0));
                uint32_t bl1 = __float_as_uint(tf32r(k1f - h1));
                mma_tf32(c[nt], aqh[ks], bl0, bl1);   // Qh*Kl
                mma_tf32(c[nt], aql[ks], bh0, bh1);   // Ql*Kh
                mma_tf32(c[nt], aqh[ks], bh0, bh1);   // Qh*Kh (dominant last)
            }
        }
        if (k0 + FN > SS) {
#pragma unroll
            for (int nt = 0; nt < 8; nt++) {
                int j0 = k0 + nt*8 + lm*2;
                if (j0 >= SS) { c[nt][0] = c[nt][1] = c[nt][2] = c[nt][3] = -1e30f; }
            }
        }
#pragma unroll
        for (int hf = 0; hf < 2; hf++) {
            float rm = -INFINITY;
#pragma unroll
            for (int nt = 0; nt < 8; nt++)
                rm = fmaxf(rm, fmaxf(c[nt][2*hf], c[nt][2*hf+1]));
            rm = fmaxf(rm, __shfl_xor_sync(0xffffffffu, rm, 1));
            rm = fmaxf(rm, __shfl_xor_sync(0xffffffffu, rm, 2));
            float mn = fmaxf(m_i[hf], rm);
            float alpha = __expf(m_i[hf] - mn);
            float rs = 0.f;
#pragma unroll
            for (int nt = 0; nt < 8; nt++) {
                float p0 = __expf(c[nt][2*hf]   - mn);
                float p1 = __expf(c[nt][2*hf+1] - mn);
                c[nt][2*hf] = p0; c[nt][2*hf+1] = p1;
                rs += p0 + p1;
            }
            rs += __shfl_xor_sync(0xffffffffu, rs, 1);
            rs += __shfl_xor_sync(0xffffffffu, rs, 2);
            l_i[hf] = l_i[hf]*alpha + rs;
            m_i[hf] = mn;
#pragma unroll
            for (int nt = 0; nt < 4; nt++) {
                o[nt][2*hf]   *= alpha;
                o[nt][2*hf+1] *= alpha;
            }
        }
        // stage P (tf32) into per-warp rows of QP
#pragma unroll
        for (int nt = 0; nt < 8; nt++) {
            *(float2*)&QP[r0+l4  ][nt*8+lm*2] = make_float2(tf32r(c[nt][0]), tf32r(c[nt][1]));
            *(float2*)&QP[r0+l4+8][nt*8+lm*2] = make_float2(tf32r(c[nt][2]), tf32r(c[nt][3]));
        }
        __syncwarp();
        // PV: o += P @ V
#pragma unroll
        for (int ks = 0; ks < 8; ks++) {
            int kk = ks*8;
            uint32_t a[4];
            a[0] = __float_as_uint(QP[r0+l4  ][kk+lm  ]);
            a[1] = __float_as_uint(QP[r0+l4+8][kk+lm  ]);
            a[2] = __float_as_uint(QP[r0+l4  ][kk+lm+4]);
            a[3] = __float_as_uint(QP[r0+l4+8][kk+lm+4]);
#pragma unroll
            for (int nt = 0; nt < 4; nt++) {
                uint32_t b0 = __float_as_uint(Vs[kk+lm  ][nt*8+l4]);
                uint32_t b1 = __float_as_uint(Vs[kk+lm+4][nt*8+l4]);
                mma_tf32(o[nt], a, b0, b1);
            }
        }
        __syncwarp();
    }

#pragma unroll
    for (int hf = 0; hf < 2; hf++) {
        int gr = q0 + r0 + l4 + hf*8;
        if (gr < SS) {
            float inv = 1.f / l_i[hf];
#pragma unroll
            for (int nt = 0; nt < 4; nt++) {
                float2 v = make_float2(o[nt][2*hf]*inv, o[nt][2*hf+1]*inv);
                *(float2*)&g_ctx[(size_t)(b*SS+gr)*DD + h*HDIM + nt*8 + lm*2] = v;
            }
        }
    }
}

// ---------------- mean-pool + out-proj ----------------
__global__ void k_pool(const float* __restrict__ Wo, const float* __restrict__ bo,
                       float* __restrict__ out) {
    __shared__ float mean[DD];
    int b = blockIdx.x, t = threadIdx.x;
    float s = 0.f;
    const float* base = g_ctx + (size_t)b*SS*DD + t;
#pragma unroll 8
    for (int si = 0; si < SS; si++) s += base[(size_t)si*DD];
    mean[t] = s * (1.f / (float)SS);
    __syncthreads();
    float acc = bo[t];
    const float* wrow = Wo + t*DD;
#pragma unroll 8
    for (int d = 0; d < DD; d++) acc += mean[d]*wrow[d];
    out[b*DD + t] = acc;
}

// ---------------- launch ----------------
extern "C" void kernel_launch(void* const* d_in, const int* in_sizes, int n_in,
                              void* d_out, int out_size) {
    const float* x    = (const float*)d_in[0];
    const float* cw   = (const float*)d_in[1];
    const float* emb  = (const float*)d_in[2];
    const float* ipw  = (const float*)d_in[3];
    const float* ipb  = (const float*)d_in[4];
    const float* opw  = (const float*)d_in[5];
    const float* opb  = (const float*)d_in[6];
    float* out = (float*)d_out;
    int full_out = (out_size >= OUT_FULL) ? 1 : 0;

    k_pe<<<SS, 256>>>();
    k_conv<<<dim3(BB, 8), 256>>>(x, cw);
    k_scan<<<1, 256>>>(1);
    k_hist2<<<256, 256>>>();
    k_scan<<<1, 256>>>(2);
    k_hist3<<<256, 256>>>();
    k_scan<<<1, 256>>>(3);
    k_sparse<<<(BB*SS + 255)/256, 256>>>(emb, out, full_out);
    k_qkv0<<<dim3(13, 12), 256>>>(ipw, ipb);
    k_delta<<<dim3((MAXACT + 63)/64, 12), 256>>>(ipw);
    k_flash<<<dim3((SS + FM - 1)/FM, NHH, BB), 128>>>();
    k_pool<<<BB, 256>>>(opw, opb, out);
}

// round 6
// speedup vs baseline: 1.8400x; 1.1164x over previous
#include <cuda_runtime.h>
#include <math.h>
#include <stdint.h>

// ---------------- problem constants ----------------
#define BB   32
#define HH   28
#define WW   28
#define C1   64
#define DD   256
#define NHH  8
#define HDIM 32
#define SS   784            // HH*WW
#define TOT  (BB*C1*SS)     // 1,605,632
#define KSEL 803            // ceil(0.0005 * TOT)
#define MAXACT 832          // >= KSEL, padded to 64

#define SW_OFF   8192                      // pooled = 32*256
#define SW_SIZE  (BB*SS*C1)                // 1,605,632
#define IDX_OFF  (SW_OFF + SW_SIZE)        // 1,613,824
#define OUT_FULL (IDX_OFF + BB*SS*2)       // 1,664,000

// ---------------- device scratch ----------------
__device__ __align__(16) float g_A[TOT];                 // conv output (B,C1,S)
__device__ __align__(16) float g_pe[SS*DD];              // positional encoding
__device__ __align__(16) float g_qkv0[SS*3*DD];          // PE @ Wqkv^T + b  (batch-invariant)
__device__ __align__(16) float g_dq[MAXACT*3*DD];        // sparse qkv deltas (compact)
__device__ __align__(16) float g_ctx[BB*SS*DD];          // attention context
__device__ __align__(16) float g_U[MAXACT*DD];           // sparse mix rows (compact)
__device__ int      g_didx[BB*SS];                       // (b,s) -> slot or -1
__device__ int      g_actrow[MAXACT];
__device__ unsigned g_hist1[2048];
__device__ unsigned g_hist2[2048];
__device__ unsigned g_hist3[1024];
__device__ unsigned g_prefix;
__device__ int      g_krem;
__device__ float    g_thresh;
__device__ int      g_nact;

__device__ __forceinline__ float tf32r(float x) {
    uint32_t o;
    asm("cvt.rna.tf32.f32 %0, %1;" : "=r"(o) : "f"(x));
    return __uint_as_float(o);
}
__device__ __forceinline__ void mma_tf32(float c[4], const uint32_t a[4],
                                         uint32_t b0, uint32_t b1) {
    asm volatile("mma.sync.aligned.m16n8k8.row.col.f32.tf32.tf32.f32 "
                 "{%0,%1,%2,%3}, {%4,%5,%6,%7}, {%8,%9}, {%0,%1,%2,%3};"
                 : "+f"(c[0]), "+f"(c[1]), "+f"(c[2]), "+f"(c[3])
                 : "r"(a[0]), "r"(a[1]), "r"(a[2]), "r"(a[3]), "r"(b0), "r"(b1));
}

// ---------------- positional encoding (+ global init in block 0) ----------------
__global__ void k_pe() {
    int s = blockIdx.x;            // 0..783
    int d = threadIdx.x;           // 0..255
    if (s == 0) {
        for (int i = d; i < 2048; i += 256) { g_hist1[i] = 0; g_hist2[i] = 0; }
        for (int i = d; i < 1024; i += 256) g_hist3[i] = 0;
        if (d == 0) { g_prefix = 0; g_krem = KSEL; g_nact = 0; g_thresh = 0.f; }
    }
    int h = s / WW, w = s % WW;
    int i2 = d & ~1;               // even base index (= 2i)
    float div = expf((float)i2 * (-logf(10000.0f) / (float)DD));
    float val = (d & 1) ? cosf((float)w * div) : sinf((float)h * div);
    g_pe[s * DD + d] = val;
}

// ---------------- conv 9x9 + relu (+ fused radix hist level 1) ----------------
__global__ void k_conv(const float* __restrict__ x, const float* __restrict__ cw) {
    __shared__ float xs[36][36];
    __shared__ float ws[8][81];
    __shared__ unsigned sh[2048];
    int b = blockIdx.x, cg = blockIdx.y;
    int t = threadIdx.x;
    for (int e = t; e < 36*36; e += 256) {
        int r = e / 36, c = e % 36;
        int hh = r - 4, ww = c - 4;
        xs[r][c] = (hh >= 0 && hh < HH && ww >= 0 && ww < WW) ? x[b*SS + hh*WW + ww] : 0.f;
    }
    for (int e = t; e < 8*81; e += 256) {
        int c8 = e / 81, k = e % 81;
        ws[c8][k] = cw[(cg*8 + c8)*81 + k];
    }
    for (int i = t; i < 2048; i += 256) sh[i] = 0;
    __syncthreads();
    for (int c8 = 0; c8 < 8; c8++) {
        for (int p = t; p < SS; p += 256) {
            int hh = p / WW, ww = p % WW;
            float acc = 0.f;
#pragma unroll
            for (int ky = 0; ky < 9; ky++)
#pragma unroll
                for (int kx = 0; kx < 9; kx++)
                    acc += xs[hh+ky][ww+kx] * ws[c8][ky*9 + kx];
            acc = fmaxf(acc, 0.f);
            g_A[((b*C1) + cg*8 + c8)*SS + p] = acc;
            unsigned u = __float_as_uint(acc);
            if (u) atomicAdd(&sh[u >> 21], 1u);
        }
    }
    __syncthreads();
    for (int i = t; i < 2048; i += 256) { unsigned v = sh[i]; if (v) atomicAdd(&g_hist1[i], v); }
}

// ---------------- radix-select histograms (levels 2,3) ----------------
__global__ void k_hist2() {
    __shared__ unsigned sh[2048];
    int t = threadIdx.x;
    for (int i = t; i < 2048; i += 256) sh[i] = 0;
    __syncthreads();
    unsigned pf = g_prefix;
    for (int idx = blockIdx.x*256 + t; idx < TOT; idx += gridDim.x*256) {
        unsigned u = __float_as_uint(g_A[idx]);
        if (u && (u >> 21) == pf) atomicAdd(&sh[(u >> 10) & 0x7FF], 1u);
    }
    __syncthreads();
    for (int i = t; i < 2048; i += 256) { unsigned v = sh[i]; if (v) atomicAdd(&g_hist2[i], v); }
}
__global__ void k_hist3() {
    __shared__ unsigned sh[1024];
    int t = threadIdx.x;
    for (int i = t; i < 1024; i += 256) sh[i] = 0;
    __syncthreads();
    unsigned pf = g_prefix;
    for (int idx = blockIdx.x*256 + t; idx < TOT; idx += gridDim.x*256) {
        unsigned u = __float_as_uint(g_A[idx]);
        if (u && (u >> 10) == pf) atomicAdd(&sh[u & 0x3FF], 1u);
    }
    __syncthreads();
    for (int i = t; i < 1024; i += 256) { unsigned v = sh[i]; if (v) atomicAdd(&g_hist3[i], v); }
}

// scan: find bin where suffix-cumulative crosses k
__global__ void k_scan(int level) {
    const unsigned* hist = (level == 1) ? g_hist1 : (level == 2) ? g_hist2 : g_hist3;
    int nbins = (level == 3) ? 1024 : 2048;
    int final_ = (level == 3);
    __shared__ unsigned part[256];
    __shared__ unsigned suf[256];
    int t = threadIdx.x;
    int chunk = nbins / 256;
    unsigned loc[8];
    unsigned psum = 0;
    for (int i = 0; i < chunk; i++) { loc[i] = hist[t*chunk + i]; psum += loc[i]; }
    part[t] = psum; suf[t] = psum;
    __syncthreads();
    for (int off = 1; off < 256; off <<= 1) {
        unsigned v = suf[t];
        if (t + off < 256) v += suf[t + off];
        __syncthreads();
        suf[t] = v;
        __syncthreads();
    }
    unsigned k = (unsigned)g_krem;
    unsigned total = suf[0];
    if (total < k) {
        if (t == 0) { if (final_) g_thresh = 0.f; else g_prefix = 0xFFFFFFFFu; }
        return;
    }
    unsigned above = suf[t] - part[t];
    if (above < k && suf[t] >= k) {
        unsigned cum = above;
        for (int i = chunk - 1; i >= 0; i--) {
            cum += loc[i];
            if (cum >= k) {
                unsigned sel = (unsigned)(t*chunk + i);
                if (final_) g_thresh = __uint_as_float((g_prefix << 10) | sel);
                else { g_prefix = (g_prefix << 11) | sel; g_krem = (int)(k - (cum - loc[i])); }
                break;
            }
        }
    }
}

// ---------------- per-pixel sparse softmax + outputs + compact U + didx ----------------
__global__ void k_sparse(const float* __restrict__ emb, float* __restrict__ out, int full_out) {
    int p = blockIdx.x*256 + threadIdx.x;
    if (p >= BB*SS) return;
    int b = p / SS, s = p % SS;
    float thr = g_thresh;
    float m1 = -INFINITY, m2 = -INFINITY;
    int i1 = 0, i2 = 0, cnt = 0;
    const float* ap = g_A + (size_t)b*C1*SS + s;
#pragma unroll 8
    for (int c = 0; c < C1; c++) {
        float a = ap[c*SS];
        float v = (a >= thr) ? a : 0.f;
        if (v > 0.f) cnt++;
        if (v > m1) { m2 = m1; i2 = i1; m1 = v; i1 = c; }
        else if (v > m2) { m2 = v; i2 = c; }
    }
    float wA = 0.f, wB = 0.f;
    if (cnt == 1) wA = 1.f;
    else if (cnt >= 2) {
        float e2 = expf(m2 - m1);
        float z = 1.f + e2;
        wA = 1.f / z; wB = e2 / z;
    }
    if (full_out) {
        float* sw = out + SW_OFF + (size_t)p*C1;
        for (int c = 0; c < C1; c++) {
            float o = 0.f;
            if (c == i1) o = wA; else if (c == i2) o = wB;
            sw[c] = o;
        }
        out[IDX_OFF + p*2]     = (float)i1;
        out[IDX_OFF + p*2 + 1] = (float)i2;
    }
    int slotw = -1;
    if (cnt > 0) {
        int slot = atomicAdd(&g_nact, 1);
        if (slot < MAXACT) {
            slotw = slot;
            g_actrow[slot] = p;
            float w2v = (cnt >= 2) ? wB : 0.f;
            float* up = g_U + (size_t)slot*DD;
            const float* e1p = emb + i1*DD;
            const float* e2p = emb + i2*DD;
            for (int d = 0; d < DD; d++) up[d] = wA*e1p[d] + w2v*e2p[d];
        }
    }
    g_didx[p] = slotw;
}

// ---------------- qkv0 = PE @ Wqkv^T + b ----------------
__global__ void k_qkv0(const float* __restrict__ Wq, const float* __restrict__ bias) {
    __shared__ float As[16][68];
    __shared__ float Bs[16][68];
    int tx = threadIdx.x % 16, ty = threadIdx.x / 16;
    int m0 = blockIdx.x*64, n0 = blockIdx.y*64;
    float acc[4][4] = {};
    int lr = threadIdx.x / 4;
    int lk = (threadIdx.x % 4) * 4;
    for (int k0 = 0; k0 < DD; k0 += 16) {
        float4 av = (m0 + lr < SS) ? *(const float4*)&g_pe[(m0+lr)*DD + k0 + lk] : make_float4(0,0,0,0);
        float4 bv = *(const float4*)&Wq[(n0+lr)*DD + k0 + lk];
        __syncthreads();
        As[lk+0][lr] = av.x; As[lk+1][lr] = av.y; As[lk+2][lr] = av.z; As[lk+3][lr] = av.w;
        Bs[lk+0][lr] = bv.x; Bs[lk+1][lr] = bv.y; Bs[lk+2][lr] = bv.z; Bs[lk+3][lr] = bv.w;
        __syncthreads();
#pragma unroll
        for (int kk = 0; kk < 16; kk++) {
            float4 a4 = *(const float4*)&As[kk][ty*4];
            float4 b4 = *(const float4*)&Bs[kk][tx*4];
            float sa[4] = {a4.x, a4.y, a4.z, a4.w};
            float sb[4] = {b4.x, b4.y, b4.z, b4.w};
#pragma unroll
            for (int i = 0; i < 4; i++)
#pragma unroll
                for (int j = 0; j < 4; j++)
                    acc[i][j] += sa[i]*sb[j];
        }
    }
#pragma unroll
    for (int i = 0; i < 4; i++) {
        int m = m0 + ty*4 + i;
        if (m < SS)
#pragma unroll
            for (int j = 0; j < 4; j++) {
                int n = n0 + tx*4 + j;
                g_qkv0[m*768 + n] = acc[i][j] + bias[n];
            }
    }
}

// ---------------- dq = U @ Wqkv^T (compact rows, no bias) ----------------
__global__ void k_delta(const float* __restrict__ Wq) {
    int nact = g_nact; if (nact > MAXACT) nact = MAXACT;
    int m0 = blockIdx.x*64;
    if (m0 >= nact) return;
    __shared__ float As[16][68];
    __shared__ float Bs[16][68];
    int tx = threadIdx.x % 16, ty = threadIdx.x / 16;
    int n0 = blockIdx.y*64;
    float acc[4][4] = {};
    int lr = threadIdx.x / 4;
    int lk = (threadIdx.x % 4) * 4;
    for (int k0 = 0; k0 < DD; k0 += 16) {
        float4 av = (m0 + lr < nact) ? *(const float4*)&g_U[(size_t)(m0+lr)*DD + k0 + lk] : make_float4(0,0,0,0);
        float4 bv = *(const float4*)&Wq[(n0+lr)*DD + k0 + lk];
        __syncthreads();
        As[lk+0][lr] = av.x; As[lk+1][lr] = av.y; As[lk+2][lr] = av.z; As[lk+3][lr] = av.w;
        Bs[lk+0][lr] = bv.x; Bs[lk+1][lr] = bv.y; Bs[lk+2][lr] = bv.z; Bs[lk+3][lr] = bv.w;
        __syncthreads();
#pragma unroll
        for (int kk = 0; kk < 16; kk++) {
            float4 a4 = *(const float4*)&As[kk][ty*4];
            float4 b4 = *(const float4*)&Bs[kk][tx*4];
            float sa[4] = {a4.x, a4.y, a4.z, a4.w};
            float sb[4] = {b4.x, b4.y, b4.z, b4.w};
#pragma unroll
            for (int i = 0; i < 4; i++)
#pragma unroll
                for (int j = 0; j < 4; j++)
                    acc[i][j] += sa[i]*sb[j];
        }
    }
#pragma unroll
    for (int i = 0; i < 4; i++) {
        int m = m0 + ty*4 + i;
        if (m < nact) {
            float* dst = g_dq + (size_t)m*768 + n0 + tx*4;
#pragma unroll
            for (int j = 0; j < 4; j++) dst[j] = acc[i][j];
        }
    }
}

// ---------------- tensor-core flash attention (3xTF32 QK, tf32 PV) ----------------
// 128 threads / 4 warps; warp owns 16 q-rows. Q hi/lo fragments in regs;
// Kh/Kl split in the loader; exp2-domain softmax (log2e folded into Q scale).
// smem = QP 17408 + Kh 9216 + Kl 9216 + Vs 10240 = 46080 < 48KB.
// launch_bounds(128,4): cap regs for 4 blocks/SM (occupancy was the R5 limiter).
#define FM 64
#define FN 64
__global__ __launch_bounds__(128, 4) void k_flash() {
    __shared__ __align__(16) float QP[FM][68];    // Q staging (cols 0..31), then P (cols 0..63)
    __shared__ __align__(16) float Kh[FN][36];
    __shared__ __align__(16) float Kl[FN][36];
    __shared__ __align__(16) float Vs[FN][40];
    int b = blockIdx.z, h = blockIdx.y;
    int q0 = blockIdx.x * FM;
    int t = threadIdx.x;
    int w = t >> 5, lane = t & 31;
    int l4 = lane >> 2, lm = lane & 3;
    // scale * log2(e): softmax done in exp2 domain
    const float scale = 0.17677669529663689f * 1.4426950408889634f;

    const int* didx = g_didx + b*SS;

    // stage scaled fp32 Q (= qkv0 + dq)
    for (int f = t; f < FM*8; f += 128) {
        int r = f >> 3, c4 = (f & 7) * 4;
        int gr = q0 + r;
        float4 v = make_float4(0.f,0.f,0.f,0.f);
        if (gr < SS) {
            v = *(const float4*)(g_qkv0 + (size_t)gr*768 + h*HDIM + c4);
            int sl = didx[gr];
            if (sl >= 0) {
                float4 d = *(const float4*)(g_dq + (size_t)sl*768 + h*HDIM + c4);
                v.x += d.x; v.y += d.y; v.z += d.z; v.w += d.w;
            }
        }
        QP[r][c4+0] = v.x*scale; QP[r][c4+1] = v.y*scale;
        QP[r][c4+2] = v.z*scale; QP[r][c4+3] = v.w*scale;
    }
    __syncthreads();

    int r0 = w * 16;
    // hoist Q hi/lo fragments: [ks][4]
    uint32_t aqh[4][4], aql[4][4];
#pragma unroll
    for (int ks = 0; ks < 4; ks++) {
        int kk = ks*8;
        float v[4];
        v[0] = QP[r0+l4  ][kk+lm  ];
        v[1] = QP[r0+l4+8][kk+lm  ];
        v[2] = QP[r0+l4  ][kk+lm+4];
        v[3] = QP[r0+l4+8][kk+lm+4];
#pragma unroll
        for (int j = 0; j < 4; j++) {
            float hi = tf32r(v[j]);
            aqh[ks][j] = __float_as_uint(hi);
            aql[ks][j] = __float_as_uint(tf32r(v[j] - hi));
        }
    }
    // from here warp w uses only QP rows [r0, r0+16) as its private P tile.

    float m_i[2], l_i[2], o[4][4];
#pragma unroll
    for (int hf = 0; hf < 2; hf++) { m_i[hf] = -INFINITY; l_i[hf] = 0.f; }
#pragma unroll
    for (int nt = 0; nt < 4; nt++)
#pragma unroll
        for (int c = 0; c < 4; c++) o[nt][c] = 0.f;

    for (int k0 = 0; k0 < SS; k0 += FN) {
        __syncthreads();   // protect Kh/Kl/Vs reuse
        for (int f = t; f < FN*8; f += 128) {
            int r = f >> 3, c4 = (f & 7) * 4;
            int gr = k0 + r;
            float4 kv = make_float4(0.f,0.f,0.f,0.f), vv = make_float4(0.f,0.f,0.f,0.f);
            if (gr < SS) {
                const float* base = g_qkv0 + (size_t)gr*768 + h*HDIM + c4;
                kv = *(const float4*)(base + DD);
                vv = *(const float4*)(base + 2*DD);
                int sl = didx[gr];
                if (sl >= 0) {
                    const float* dbase = g_dq + (size_t)sl*768 + h*HDIM + c4;
                    float4 dk = *(const float4*)(dbase + DD);
                    float4 dv = *(const float4*)(dbase + 2*DD);
                    kv.x += dk.x; kv.y += dk.y; kv.z += dk.z; kv.w += dk.w;
                    vv.x += dv.x; vv.y += dv.y; vv.z += dv.z; vv.w += dv.w;
                }
            }
            float h0 = tf32r(kv.x), h1 = tf32r(kv.y), h2 = tf32r(kv.z), h3 = tf32r(kv.w);
            Kh[r][c4+0] = h0; Kh[r][c4+1] = h1; Kh[r][c4+2] = h2; Kh[r][c4+3] = h3;
            Kl[r][c4+0] = tf32r(kv.x - h0); Kl[r][c4+1] = tf32r(kv.y - h1);
            Kl[r][c4+2] = tf32r(kv.z - h2); Kl[r][c4+3] = tf32r(kv.w - h3);
            Vs[r][c4+0] = tf32r(vv.x); Vs[r][c4+1] = tf32r(vv.y);
            Vs[r][c4+2] = tf32r(vv.z); Vs[r][c4+3] = tf32r(vv.w);
        }
        __syncthreads();

        float c[8][4];
#pragma unroll
        for (int nt = 0; nt < 8; nt++) {
            c[nt][0] = c[nt][1] = c[nt][2] = c[nt][3] = 0.f;
#pragma unroll
            for (int ks = 0; ks < 4; ks++) {
                int kk = ks*8;
                int kr = nt*8 + l4;
                uint32_t bh0 = __float_as_uint(Kh[kr][kk+lm  ]);
                uint32_t bh1 = __float_as_uint(Kh[kr][kk+lm+4]);
                uint32_t bl0 = __float_as_uint(Kl[kr][kk+lm  ]);
                uint32_t bl1 = __float_as_uint(Kl[kr][kk+lm+4]);
                mma_tf32(c[nt], aqh[ks], bl0, bl1);   // Qh*Kl
                mma_tf32(c[nt], aql[ks], bh0, bh1);   // Ql*Kh
                mma_tf32(c[nt], aqh[ks], bh0, bh1);   // Qh*Kh (dominant last)
            }
        }
        if (k0 + FN > SS) {
#pragma unroll
            for (int nt = 0; nt < 8; nt++) {
                int j0 = k0 + nt*8 + lm*2;
                if (j0 >= SS) { c[nt][0] = c[nt][1] = c[nt][2] = c[nt][3] = -1e30f; }
            }
        }
#pragma unroll
        for (int hf = 0; hf < 2; hf++) {
            float rm = -INFINITY;
#pragma unroll
            for (int nt = 0; nt < 8; nt++)
                rm = fmaxf(rm, fmaxf(c[nt][2*hf], c[nt][2*hf+1]));
            rm = fmaxf(rm, __shfl_xor_sync(0xffffffffu, rm, 1));
            rm = fmaxf(rm, __shfl_xor_sync(0xffffffffu, rm, 2));
            float mn = fmaxf(m_i[hf], rm);
            float alpha = exp2f(m_i[hf] - mn);
            float rs = 0.f;
#pragma unroll
            for (int nt = 0; nt < 8; nt++) {
                float p0 = exp2f(c[nt][2*hf]   - mn);
                float p1 = exp2f(c[nt][2*hf+1] - mn);
                c[nt][2*hf] = p0; c[nt][2*hf+1] = p1;
                rs += p0 + p1;
            }
            rs += __shfl_xor_sync(0xffffffffu, rs, 1);
            rs += __shfl_xor_sync(0xffffffffu, rs, 2);
            l_i[hf] = l_i[hf]*alpha + rs;
            m_i[hf] = mn;
#pragma unroll
            for (int nt = 0; nt < 4; nt++) {
                o[nt][2*hf]   *= alpha;
                o[nt][2*hf+1] *= alpha;
            }
        }
        // stage P (tf32) into per-warp rows of QP
#pragma unroll
        for (int nt = 0; nt < 8; nt++) {
            *(float2*)&QP[r0+l4  ][nt*8+lm*2] = make_float2(tf32r(c[nt][0]), tf32r(c[nt][1]));
            *(float2*)&QP[r0+l4+8][nt*8+lm*2] = make_float2(tf32r(c[nt][2]), tf32r(c[nt][3]));
        }
        __syncwarp();
        // PV: o += P @ V
#pragma unroll
        for (int ks = 0; ks < 8; ks++) {
            int kk = ks*8;
            uint32_t a[4];
            a[0] = __float_as_uint(QP[r0+l4  ][kk+lm  ]);
            a[1] = __float_as_uint(QP[r0+l4+8][kk+lm  ]);
            a[2] = __float_as_uint(QP[r0+l4  ][kk+lm+4]);
            a[3] = __float_as_uint(QP[r0+l4+8][kk+lm+4]);
#pragma unroll
            for (int nt = 0; nt < 4; nt++) {
                uint32_t b0 = __float_as_uint(Vs[kk+lm  ][nt*8+l4]);
                uint32_t b1 = __float_as_uint(Vs[kk+lm+4][nt*8+l4]);
                mma_tf32(o[nt], a, b0, b1);
            }
        }
        __syncwarp();
    }

#pragma unroll
    for (int hf = 0; hf < 2; hf++) {
        int gr = q0 + r0 + l4 + hf*8;
        if (gr < SS) {
            float inv = 1.f / l_i[hf];
#pragma unroll
            for (int nt = 0; nt < 4; nt++) {
                float2 v = make_float2(o[nt][2*hf]*inv, o[nt][2*hf+1]*inv);
                *(float2*)&g_ctx[(size_t)(b*SS+gr)*DD + h*HDIM + nt*8 + lm*2] = v;
            }
        }
    }
}

// ---------------- mean-pool + out-proj ----------------
__global__ void k_pool(const float* __restrict__ Wo, const float* __restrict__ bo,
                       float* __restrict__ out) {
    __shared__ float mean[DD];
    int b = blockIdx.x, t = threadIdx.x;
    float s = 0.f;
    const float* base = g_ctx + (size_t)b*SS*DD + t;
#pragma unroll 8
    for (int si = 0; si < SS; si++) s += base[(size_t)si*DD];
    mean[t] = s * (1.f / (float)SS);
    __syncthreads();
    float acc = bo[t];
    const float* wrow = Wo + t*DD;
#pragma unroll 8
    for (int d = 0; d < DD; d++) acc += mean[d]*wrow[d];
    out[b*DD + t] = acc;
}

// ---------------- launch ----------------
extern "C" void kernel_launch(void* const* d_in, const int* in_sizes, int n_in,
                              void* d_out, int out_size) {
    const float* x    = (const float*)d_in[0];
    const float* cw   = (const float*)d_in[1];
    const float* emb  = (const float*)d_in[2];
    const float* ipw  = (const float*)d_in[3];
    const float* ipb  = (const float*)d_in[4];
    const float* opw  = (const float*)d_in[5];
    const float* opb  = (const float*)d_in[6];
    float* out = (float*)d_out;
    int full_out = (out_size >= OUT_FULL) ? 1 : 0;

    k_pe<<<SS, 256>>>();
    k_conv<<<dim3(BB, 8), 256>>>(x, cw);
    k_scan<<<1, 256>>>(1);
    k_hist2<<<256, 256>>>();
    k_scan<<<1, 256>>>(2);
    k_hist3<<<256, 256>>>();
    k_scan<<<1, 256>>>(3);
    k_sparse<<<(BB*SS + 255)/256, 256>>>(emb, out, full_out);
    k_qkv0<<<dim3(13, 12), 256>>>(ipw, ipb);
    k_delta<<<dim3((MAXACT + 63)/64, 12), 256>>>(ipw);
    k_flash<<<dim3((SS + FM - 1)/FM, NHH, BB), 128>>>();
    k_pool<<<BB, 256>>>(opw, opb, out);
}

// round 7
// speedup vs baseline: 2.2750x; 1.2364x over previous
#include <cuda_runtime.h>
#include <cuda_fp16.h>
#include <math.h>
#include <stdint.h>

// ---------------- problem constants ----------------
#define BB   32
#define HH   28
#define WW   28
#define C1   64
#define DD   256
#define NHH  8
#define HDIM 32
#define SS   784            // HH*WW
#define TOT  (BB*C1*SS)     // 1,605,632
#define KSEL 803            // ceil(0.0005 * TOT)
#define MAXACT 832          // >= KSEL, padded to 64

#define SW_OFF   8192                      // pooled = 32*256
#define SW_SIZE  (BB*SS*C1)                // 1,605,632
#define IDX_OFF  (SW_OFF + SW_SIZE)        // 1,613,824
#define OUT_FULL (IDX_OFF + BB*SS*2)       // 1,664,000

// ---------------- device scratch ----------------
__device__ __align__(16) float g_A[TOT];                 // conv output (B,C1,S)
__device__ __align__(16) float g_pe[SS*DD];              // positional encoding
__device__ __align__(16) float g_qkv0[SS*3*DD];          // PE @ Wqkv^T + b  (batch-invariant)
__device__ __align__(16) float g_dq[MAXACT*3*DD];        // sparse qkv deltas (compact)
__device__ __align__(16) float g_ctx[BB*SS*DD];          // attention context
__device__ __align__(16) float g_U[MAXACT*DD];           // sparse mix rows (compact)
__device__ int      g_didx[BB*SS];                       // (b,s) -> slot or -1
__device__ int      g_actrow[MAXACT];
__device__ unsigned g_hist1[2048];
__device__ unsigned g_hist2[2048];
__device__ unsigned g_hist3[1024];
__device__ unsigned g_prefix;
__device__ int      g_krem;
__device__ float    g_thresh;
__device__ int      g_nact;

__device__ __forceinline__ void mma_f16(float c[4], const uint32_t a[4],
                                        uint32_t b0, uint32_t b1) {
    asm volatile("mma.sync.aligned.m16n8k16.row.col.f32.f16.f16.f32 "
                 "{%0,%1,%2,%3}, {%4,%5,%6,%7}, {%8,%9}, {%0,%1,%2,%3};"
                 : "+f"(c[0]), "+f"(c[1]), "+f"(c[2]), "+f"(c[3])
                 : "r"(a[0]), "r"(a[1]), "r"(a[2]), "r"(a[3]), "r"(b0), "r"(b1));
}

// ---------------- positional encoding (+ global init in block 0) ----------------
__global__ void k_pe() {
    int s = blockIdx.x;            // 0..783
    int d = threadIdx.x;           // 0..255
    if (s == 0) {
        for (int i = d; i < 2048; i += 256) { g_hist1[i] = 0; g_hist2[i] = 0; }
        for (int i = d; i < 1024; i += 256) g_hist3[i] = 0;
        if (d == 0) { g_prefix = 0; g_krem = KSEL; g_nact = 0; g_thresh = 0.f; }
    }
    int h = s / WW, w = s % WW;
    int i2 = d & ~1;               // even base index (= 2i)
    float div = expf((float)i2 * (-logf(10000.0f) / (float)DD));
    float val = (d & 1) ? cosf((float)w * div) : sinf((float)h * div);
    g_pe[s * DD + d] = val;
}

// ---------------- conv 9x9 + relu (+ fused radix hist level 1) ----------------
__global__ void k_conv(const float* __restrict__ x, const float* __restrict__ cw) {
    __shared__ float xs[36][36];
    __shared__ float ws[8][81];
    __shared__ unsigned sh[2048];
    int b = blockIdx.x, cg = blockIdx.y;
    int t = threadIdx.x;
    for (int e = t; e < 36*36; e += 256) {
        int r = e / 36, c = e % 36;
        int hh = r - 4, ww = c - 4;
        xs[r][c] = (hh >= 0 && hh < HH && ww >= 0 && ww < WW) ? x[b*SS + hh*WW + ww] : 0.f;
    }
    for (int e = t; e < 8*81; e += 256) {
        int c8 = e / 81, k = e % 81;
        ws[c8][k] = cw[(cg*8 + c8)*81 + k];
    }
    for (int i = t; i < 2048; i += 256) sh[i] = 0;
    __syncthreads();
    for (int c8 = 0; c8 < 8; c8++) {
        for (int p = t; p < SS; p += 256) {
            int hh = p / WW, ww = p % WW;
            float acc = 0.f;
#pragma unroll
            for (int ky = 0; ky < 9; ky++)
#pragma unroll
                for (int kx = 0; kx < 9; kx++)
                    acc += xs[hh+ky][ww+kx] * ws[c8][ky*9 + kx];
            acc = fmaxf(acc, 0.f);
            g_A[((b*C1) + cg*8 + c8)*SS + p] = acc;
            unsigned u = __float_as_uint(acc);
            if (u) atomicAdd(&sh[u >> 21], 1u);
        }
    }
    __syncthreads();
    for (int i = t; i < 2048; i += 256) { unsigned v = sh[i]; if (v) atomicAdd(&g_hist1[i], v); }
}

// ---------------- radix-select histograms (levels 2,3) ----------------
__global__ void k_hist2() {
    __shared__ unsigned sh[2048];
    int t = threadIdx.x;
    for (int i = t; i < 2048; i += 256) sh[i] = 0;
    __syncthreads();
    unsigned pf = g_prefix;
    for (int idx = blockIdx.x*256 + t; idx < TOT; idx += gridDim.x*256) {
        unsigned u = __float_as_uint(g_A[idx]);
        if (u && (u >> 21) == pf) atomicAdd(&sh[(u >> 10) & 0x7FF], 1u);
    }
    __syncthreads();
    for (int i = t; i < 2048; i += 256) { unsigned v = sh[i]; if (v) atomicAdd(&g_hist2[i], v); }
}
__global__ void k_hist3() {
    __shared__ unsigned sh[1024];
    int t = threadIdx.x;
    for (int i = t; i < 1024; i += 256) sh[i] = 0;
    __syncthreads();
    unsigned pf = g_prefix;
    for (int idx = blockIdx.x*256 + t; idx < TOT; idx += gridDim.x*256) {
        unsigned u = __float_as_uint(g_A[idx]);
        if (u && (u >> 10) == pf) atomicAdd(&sh[u & 0x3FF], 1u);
    }
    __syncthreads();
    for (int i = t; i < 1024; i += 256) { unsigned v = sh[i]; if (v) atomicAdd(&g_hist3[i], v); }
}

// scan: find bin where suffix-cumulative crosses k
__global__ void k_scan(int level) {
    const unsigned* hist = (level == 1) ? g_hist1 : (level == 2) ? g_hist2 : g_hist3;
    int nbins = (level == 3) ? 1024 : 2048;
    int final_ = (level == 3);
    __shared__ unsigned part[256];
    __shared__ unsigned suf[256];
    int t = threadIdx.x;
    int chunk = nbins / 256;
    unsigned loc[8];
    unsigned psum = 0;
    for (int i = 0; i < chunk; i++) { loc[i] = hist[t*chunk + i]; psum += loc[i]; }
    part[t] = psum; suf[t] = psum;
    __syncthreads();
    for (int off = 1; off < 256; off <<= 1) {
        unsigned v = suf[t];
        if (t + off < 256) v += suf[t + off];
        __syncthreads();
        suf[t] = v;
        __syncthreads();
    }
    unsigned k = (unsigned)g_krem;
    unsigned total = suf[0];
    if (total < k) {
        if (t == 0) { if (final_) g_thresh = 0.f; else g_prefix = 0xFFFFFFFFu; }
        return;
    }
    unsigned above = suf[t] - part[t];
    if (above < k && suf[t] >= k) {
        unsigned cum = above;
        for (int i = chunk - 1; i >= 0; i--) {
            cum += loc[i];
            if (cum >= k) {
                unsigned sel = (unsigned)(t*chunk + i);
                if (final_) g_thresh = __uint_as_float((g_prefix << 10) | sel);
                else { g_prefix = (g_prefix << 11) | sel; g_krem = (int)(k - (cum - loc[i])); }
                break;
            }
        }
    }
}

// ---------------- per-pixel sparse softmax + outputs + compact U + didx ----------------
__global__ void k_sparse(const float* __restrict__ emb, float* __restrict__ out, int full_out) {
    int p = blockIdx.x*256 + threadIdx.x;
    if (p >= BB*SS) return;
    int b = p / SS, s = p % SS;
    float thr = g_thresh;
    float m1 = -INFINITY, m2 = -INFINITY;
    int i1 = 0, i2 = 0, cnt = 0;
    const float* ap = g_A + (size_t)b*C1*SS + s;
#pragma unroll 8
    for (int c = 0; c < C1; c++) {
        float a = ap[c*SS];
        float v = (a >= thr) ? a : 0.f;
        if (v > 0.f) cnt++;
        if (v > m1) { m2 = m1; i2 = i1; m1 = v; i1 = c; }
        else if (v > m2) { m2 = v; i2 = c; }
    }
    float wA = 0.f, wB = 0.f;
    if (cnt == 1) wA = 1.f;
    else if (cnt >= 2) {
        float e2 = expf(m2 - m1);
        float z = 1.f + e2;
        wA = 1.f / z; wB = e2 / z;
    }
    if (full_out) {
        float* sw = out + SW_OFF + (size_t)p*C1;
        for (int c = 0; c < C1; c++) {
            float o = 0.f;
            if (c == i1) o = wA; else if (c == i2) o = wB;
            sw[c] = o;
        }
        out[IDX_OFF + p*2]     = (float)i1;
        out[IDX_OFF + p*2 + 1] = (float)i2;
    }
    int slotw = -1;
    if (cnt > 0) {
        int slot = atomicAdd(&g_nact, 1);
        if (slot < MAXACT) {
            slotw = slot;
            g_actrow[slot] = p;
            float w2v = (cnt >= 2) ? wB : 0.f;
            float* up = g_U + (size_t)slot*DD;
            const float* e1p = emb + i1*DD;
            const float* e2p = emb + i2*DD;
            for (int d = 0; d < DD; d++) up[d] = wA*e1p[d] + w2v*e2p[d];
        }
    }
    g_didx[p] = slotw;
}

// ---------------- qkv0 = PE @ Wqkv^T + b ----------------
__global__ void k_qkv0(const float* __restrict__ Wq, const float* __restrict__ bias) {
    __shared__ float As[16][68];
    __shared__ float Bs[16][68];
    int tx = threadIdx.x % 16, ty = threadIdx.x / 16;
    int m0 = blockIdx.x*64, n0 = blockIdx.y*64;
    float acc[4][4] = {};
    int lr = threadIdx.x / 4;
    int lk = (threadIdx.x % 4) * 4;
    for (int k0 = 0; k0 < DD; k0 += 16) {
        float4 av = (m0 + lr < SS) ? *(const float4*)&g_pe[(m0+lr)*DD + k0 + lk] : make_float4(0,0,0,0);
        float4 bv = *(const float4*)&Wq[(n0+lr)*DD + k0 + lk];
        __syncthreads();
        As[lk+0][lr] = av.x; As[lk+1][lr] = av.y; As[lk+2][lr] = av.z; As[lk+3][lr] = av.w;
        Bs[lk+0][lr] = bv.x; Bs[lk+1][lr] = bv.y; Bs[lk+2][lr] = bv.z; Bs[lk+3][lr] = bv.w;
        __syncthreads();
#pragma unroll
        for (int kk = 0; kk < 16; kk++) {
            float4 a4 = *(const float4*)&As[kk][ty*4];
            float4 b4 = *(const float4*)&Bs[kk][tx*4];
            float sa[4] = {a4.x, a4.y, a4.z, a4.w};
            float sb[4] = {b4.x, b4.y, b4.z, b4.w};
#pragma unroll
            for (int i = 0; i < 4; i++)
#pragma unroll
                for (int j = 0; j < 4; j++)
                    acc[i][j] += sa[i]*sb[j];
        }
    }
#pragma unroll
    for (int i = 0; i < 4; i++) {
        int m = m0 + ty*4 + i;
        if (m < SS)
#pragma unroll
            for (int j = 0; j < 4; j++) {
                int n = n0 + tx*4 + j;
                g_qkv0[m*768 + n] = acc[i][j] + bias[n];
            }
    }
}

// ---------------- dq = U @ Wqkv^T (compact rows, no bias) ----------------
__global__ void k_delta(const float* __restrict__ Wq) {
    int nact = g_nact; if (nact > MAXACT) nact = MAXACT;
    int m0 = blockIdx.x*64;
    if (m0 >= nact) return;
    __shared__ float As[16][68];
    __shared__ float Bs[16][68];
    int tx = threadIdx.x % 16, ty = threadIdx.x / 16;
    int n0 = blockIdx.y*64;
    float acc[4][4] = {};
    int lr = threadIdx.x / 4;
    int lk = (threadIdx.x % 4) * 4;
    for (int k0 = 0; k0 < DD; k0 += 16) {
        float4 av = (m0 + lr < nact) ? *(const float4*)&g_U[(size_t)(m0+lr)*DD + k0 + lk] : make_float4(0,0,0,0);
        float4 bv = *(const float4*)&Wq[(n0+lr)*DD + k0 + lk];
        __syncthreads();
        As[lk+0][lr] = av.x; As[lk+1][lr] = av.y; As[lk+2][lr] = av.z; As[lk+3][lr] = av.w;
        Bs[lk+0][lr] = bv.x; Bs[lk+1][lr] = bv.y; Bs[lk+2][lr] = bv.z; Bs[lk+3][lr] = bv.w;
        __syncthreads();
#pragma unroll
        for (int kk = 0; kk < 16; kk++) {
            float4 a4 = *(const float4*)&As[kk][ty*4];
            float4 b4 = *(const float4*)&Bs[kk][tx*4];
            float sa[4] = {a4.x, a4.y, a4.z, a4.w};
            float sb[4] = {b4.x, b4.y, b4.z, b4.w};
#pragma unroll
            for (int i = 0; i < 4; i++)
#pragma unroll
                for (int j = 0; j < 4; j++)
                    acc[i][j] += sa[i]*sb[j];
        }
    }
#pragma unroll
    for (int i = 0; i < 4; i++) {
        int m = m0 + ty*4 + i;
        if (m < nact) {
            float* dst = g_dq + (size_t)m*768 + n0 + tx*4;
#pragma unroll
            for (int j = 0; j < 4; j++) dst[j] = acc[i][j];
        }
    }
}

// ---------------- tensor-core flash attention (fp16 m16n8k16) ----------------
// QK^T: Dekker 2-way fp16 split (3 MMAs per k16) ~ 22-bit precision.
// PV: single fp16 (11-bit mantissa, same as tf32). fp32 accumulate throughout.
// 128 threads / 4 warps; warp owns 16 q-rows; exp2-domain softmax.
// smem: Qs 9216 + Ps2 9216 + Kh2 5120 + Kl2 5120 + Vst 4608 = 33280 B.
#define FM 64
#define FN 64
__global__ __launch_bounds__(128, 4) void k_flash() {
    __shared__ __align__(16) float   Qs[FM][36];     // fp32 Q staging
    __shared__ __align__(16) __half2 Ps2[FM][36];    // P tiles (per-warp rows)
    __shared__ __align__(16) __half2 Kh2[FN][20];    // K hi  (16 half2 dims + pad)
    __shared__ __align__(16) __half2 Kl2[FN][20];    // K lo
    __shared__ __align__(16) __half  Vst[32][72];    // V^T: [dim][key] + pad
    int b = blockIdx.z, h = blockIdx.y;
    int q0 = blockIdx.x * FM;
    int t = threadIdx.x;
    int w = t >> 5, lane = t & 31;
    int l4 = lane >> 2, lm = lane & 3;
    const float scale = 0.17677669529663689f * 1.4426950408889634f;  // /sqrt(32)*log2e

    const int* didx = g_didx + b*SS;

    // stage scaled fp32 Q (= qkv0 + dq)
    for (int f = t; f < FM*8; f += 128) {
        int r = f >> 3, c4 = (f & 7) * 4;
        int gr = q0 + r;
        float4 v = make_float4(0.f,0.f,0.f,0.f);
        if (gr < SS) {
            v = *(const float4*)(g_qkv0 + (size_t)gr*768 + h*HDIM + c4);
            int sl = didx[gr];
            if (sl >= 0) {
                float4 d = *(const float4*)(g_dq + (size_t)sl*768 + h*HDIM + c4);
                v.x += d.x; v.y += d.y; v.z += d.z; v.w += d.w;
            }
        }
        Qs[r][c4+0] = v.x*scale; Qs[r][c4+1] = v.y*scale;
        Qs[r][c4+2] = v.z*scale; Qs[r][c4+3] = v.w*scale;
    }
    __syncthreads();

    int r0 = w * 16;
    // hoist Q hi/lo fp16 fragments for m16n8k16: [ks][4], ks=0..1 (k16 chunks)
    uint32_t aqh[2][4], aql[2][4];
#pragma unroll
    for (int ks = 0; ks < 2; ks++) {
        int kk = ks*16;
        float p0[4], p1[4];   // element pairs (col, col+1) for a0..a3
        p0[0] = Qs[r0+l4  ][kk+2*lm  ];  p1[0] = Qs[r0+l4  ][kk+2*lm+1];
        p0[1] = Qs[r0+l4+8][kk+2*lm  ];  p1[1] = Qs[r0+l4+8][kk+2*lm+1];
        p0[2] = Qs[r0+l4  ][kk+2*lm+8];  p1[2] = Qs[r0+l4  ][kk+2*lm+9];
        p0[3] = Qs[r0+l4+8][kk+2*lm+8];  p1[3] = Qs[r0+l4+8][kk+2*lm+9];
#pragma unroll
        for (int j = 0; j < 4; j++) {
            __half h0 = __float2half_rn(p0[j]);
            __half h1 = __float2half_rn(p1[j]);
            __half l0 = __float2half_rn(p0[j] - __half2float(h0));
            __half l1 = __float2half_rn(p1[j] - __half2float(h1));
            __half2 hh = __halves2half2(h0, h1);
            __half2 ll = __halves2half2(l0, l1);
            aqh[ks][j] = *(uint32_t*)&hh;
            aql[ks][j] = *(uint32_t*)&ll;
        }
    }
    // warp w uses only Ps2 rows [r0, r0+16) as its private P tile.

    float m_i[2], l_i[2], o[4][4];
#pragma unroll
    for (int hf = 0; hf < 2; hf++) { m_i[hf] = -INFINITY; l_i[hf] = 0.f; }
#pragma unroll
    for (int nt = 0; nt < 4; nt++)
#pragma unroll
        for (int c = 0; c < 4; c++) o[nt][c] = 0.f;

    for (int k0 = 0; k0 < SS; k0 += FN) {
        __syncthreads();   // protect K/V smem reuse
        for (int f = t; f < FN*8; f += 128) {
            int r = f >> 3, c4 = (f & 7) * 4;
            int gr = k0 + r;
            float4 kv = make_float4(0.f,0.f,0.f,0.f), vv = make_float4(0.f,0.f,0.f,0.f);
            if (gr < SS) {
                const float* base = g_qkv0 + (size_t)gr*768 + h*HDIM + c4;
                kv = *(const float4*)(base + DD);
                vv = *(const float4*)(base + 2*DD);
                int sl = didx[gr];
                if (sl >= 0) {
                    const float* dbase = g_dq + (size_t)sl*768 + h*HDIM + c4;
                    float4 dk = *(const float4*)(dbase + DD);
                    float4 dv = *(const float4*)(dbase + 2*DD);
                    kv.x += dk.x; kv.y += dk.y; kv.z += dk.z; kv.w += dk.w;
                    vv.x += dv.x; vv.y += dv.y; vv.z += dv.z; vv.w += dv.w;
                }
            }
            __half h0 = __float2half_rn(kv.x), h1 = __float2half_rn(kv.y);
            __half h2 = __float2half_rn(kv.z), h3 = __float2half_rn(kv.w);
            Kh2[r][c4/2  ] = __halves2half2(h0, h1);
            Kh2[r][c4/2+1] = __halves2half2(h2, h3);
            Kl2[r][c4/2  ] = __halves2half2(__float2half_rn(kv.x - __half2float(h0)),
                                            __float2half_rn(kv.y - __half2float(h1)));
            Kl2[r][c4/2+1] = __halves2half2(__float2half_rn(kv.z - __half2float(h2)),
                                            __float2half_rn(kv.w - __half2float(h3)));
            Vst[c4+0][r] = __float2half_rn(vv.x);
            Vst[c4+1][r] = __float2half_rn(vv.y);
            Vst[c4+2][r] = __float2half_rn(vv.z);
            Vst[c4+3][r] = __float2half_rn(vv.w);
        }
        __syncthreads();

        float c[8][4];
#pragma unroll
        for (int nt = 0; nt < 8; nt++) {
            c[nt][0] = c[nt][1] = c[nt][2] = c[nt][3] = 0.f;
            int kr = nt*8 + l4;
#pragma unroll
            for (int ks = 0; ks < 2; ks++) {
                int kk2 = ks*8;
                uint32_t bh0 = *(const uint32_t*)&Kh2[kr][kk2+lm  ];
                uint32_t bh1 = *(const uint32_t*)&Kh2[kr][kk2+lm+4];
                uint32_t bl0 = *(const uint32_t*)&Kl2[kr][kk2+lm  ];
                uint32_t bl1 = *(const uint32_t*)&Kl2[kr][kk2+lm+4];
                mma_f16(c[nt], aqh[ks], bl0, bl1);   // Qh*Kl
                mma_f16(c[nt], aql[ks], bh0, bh1);   // Ql*Kh
                mma_f16(c[nt], aqh[ks], bh0, bh1);   // Qh*Kh (dominant last)
            }
        }
        if (k0 + FN > SS) {
#pragma unroll
            for (int nt = 0; nt < 8; nt++) {
                int j0 = k0 + nt*8 + lm*2;
                if (j0 >= SS) { c[nt][0] = c[nt][1] = c[nt][2] = c[nt][3] = -1e30f; }
            }
        }
#pragma unroll
        for (int hf = 0; hf < 2; hf++) {
            float rm = -INFINITY;
#pragma unroll
            for (int nt = 0; nt < 8; nt++)
                rm = fmaxf(rm, fmaxf(c[nt][2*hf], c[nt][2*hf+1]));
            rm = fmaxf(rm, __shfl_xor_sync(0xffffffffu, rm, 1));
            rm = fmaxf(rm, __shfl_xor_sync(0xffffffffu, rm, 2));
            float mn = fmaxf(m_i[hf], rm);
            float alpha = exp2f(m_i[hf] - mn);
            float rs = 0.f;
#pragma unroll
            for (int nt = 0; nt < 8; nt++) {
                float p0 = exp2f(c[nt][2*hf]   - mn);
                float p1 = exp2f(c[nt][2*hf+1] - mn);
                c[nt][2*hf] = p0; c[nt][2*hf+1] = p1;
                rs += p0 + p1;
            }
            rs += __shfl_xor_sync(0xffffffffu, rs, 1);
            rs += __shfl_xor_sync(0xffffffffu, rs, 2);
            l_i[hf] = l_i[hf]*alpha + rs;
            m_i[hf] = mn;
#pragma unroll
            for (int nt = 0; nt < 4; nt++) {
                o[nt][2*hf]   *= alpha;
                o[nt][2*hf+1] *= alpha;
            }
        }
        // stage P as half2 into per-warp rows of Ps2
#pragma unroll
        for (int nt = 0; nt < 8; nt++) {
            Ps2[r0+l4  ][nt*4+lm] = __floats2half2_rn(c[nt][0], c[nt][1]);
            Ps2[r0+l4+8][nt*4+lm] = __floats2half2_rn(c[nt][2], c[nt][3]);
        }
        __syncwarp();
        // PV: o += P @ V   (4 k16 steps over 64 keys)
#pragma unroll
        for (int ks = 0; ks < 4; ks++) {
            int kk2 = ks*8;        // half2 pair base (= 16 keys)
            int kk  = ks*16;       // key base
            uint32_t a[4];
            a[0] = *(const uint32_t*)&Ps2[r0+l4  ][kk2+lm  ];
            a[1] = *(const uint32_t*)&Ps2[r0+l4+8][kk2+lm  ];
            a[2] = *(const uint32_t*)&Ps2[r0+l4  ][kk2+lm+4];
            a[3] = *(const uint32_t*)&Ps2[r0+l4+8][kk2+lm+4];
#pragma unroll
            for (int nt = 0; nt < 4; nt++) {
                uint32_t b0 = *(const uint32_t*)&Vst[nt*8+l4][kk + 2*lm    ];
                uint32_t b1 = *(const uint32_t*)&Vst[nt*8+l4][kk + 2*lm + 8];
                mma_f16(o[nt], a, b0, b1);
            }
        }
        __syncwarp();
    }

#pragma unroll
    for (int hf = 0; hf < 2; hf++) {
        int gr = q0 + r0 + l4 + hf*8;
        if (gr < SS) {
            float inv = 1.f / l_i[hf];
#pragma unroll
            for (int nt = 0; nt < 4; nt++) {
                float2 v = make_float2(o[nt][2*hf]*inv, o[nt][2*hf+1]*inv);
                *(float2*)&g_ctx[(size_t)(b*SS+gr)*DD + h*HDIM + nt*8 + lm*2] = v;
            }
        }
    }
}

// ---------------- mean-pool + out-proj ----------------
__global__ void k_pool(const float* __restrict__ Wo, const float* __restrict__ bo,
                       float* __restrict__ out) {
    __shared__ float mean[DD];
    int b = blockIdx.x, t = threadIdx.x;
    float s = 0.f;
    const float* base = g_ctx + (size_t)b*SS*DD + t;
#pragma unroll 8
    for (int si = 0; si < SS; si++) s += base[(size_t)si*DD];
    mean[t] = s * (1.f / (float)SS);
    __syncthreads();
    float acc = bo[t];
    const float* wrow = Wo + t*DD;
#pragma unroll 8
    for (int d = 0; d < DD; d++) acc += mean[d]*wrow[d];
    out[b*DD + t] = acc;
}

// ---------------- launch ----------------
extern "C" void kernel_launch(void* const* d_in, const int* in_sizes, int n_in,
                              void* d_out, int out_size) {
    const float* x    = (const float*)d_in[0];
    const float* cw   = (const float*)d_in[1];
    const float* emb  = (const float*)d_in[2];
    const float* ipw  = (const float*)d_in[3];
    const float* ipb  = (const float*)d_in[4];
    const float* opw  = (const float*)d_in[5];
    const float* opb  = (const float*)d_in[6];
    float* out = (float*)d_out;
    int full_out = (out_size >= OUT_FULL) ? 1 : 0;

    k_pe<<<SS, 256>>>();
    k_conv<<<dim3(BB, 8), 256>>>(x, cw);
    k_scan<<<1, 256>>>(1);
    k_hist2<<<256, 256>>>();
    k_scan<<<1, 256>>>(2);
    k_hist3<<<256, 256>>>();
    k_scan<<<1, 256>>>(3);
    k_sparse<<<(BB*SS + 255)/256, 256>>>(emb, out, full_out);
    k_qkv0<<<dim3(13, 12), 256>>>(ipw, ipb);
    k_delta<<<dim3((MAXACT + 63)/64, 12), 256>>>(ipw);
    k_flash<<<dim3((SS + FM - 1)/FM, NHH, BB), 128>>>();
    k_pool<<<BB, 256>>>(opw, opb, out);
}